// round 15
// baseline (speedup 1.0000x reference)
#include <cuda_runtime.h>
#include <cuda_bf16.h>
#include <math.h>
#include <stdint.h>

#define NN 50000
#define EE 800000
#define CC 40

// ---------------- scratch (device globals; no allocations allowed) ----------------
__device__ __align__(16) float g_feat0[NN * 256];
__device__ __align__(16) float g_feat1[NN * 256];
__device__ __align__(16) float g_el0[NN * 4];
__device__ __align__(16) float g_er0[NN * 4];
__device__ __align__(16) float g_el1[NN * 4];
__device__ __align__(16) float g_er1[NN * 4];
__device__ __align__(16) __nv_bfloat16 g_xhi[NN * 256];
__device__ __align__(16) __nv_bfloat16 g_xlo[NN * 256];
__device__ __align__(16) __nv_bfloat16 g_hhi0[NN * 256];
__device__ __align__(16) __nv_bfloat16 g_hlo0[NN * 256];
__device__ __align__(16) __nv_bfloat16 g_hhi1[NN * 256];
__device__ __align__(16) __nv_bfloat16 g_hlo1[NN * 256];
__device__ __align__(16) __nv_bfloat16 g_whi0[256 * 256];
__device__ __align__(16) __nv_bfloat16 g_wlo0[256 * 256];
__device__ __align__(16) __nv_bfloat16 g_whi1[256 * 256];
__device__ __align__(16) __nv_bfloat16 g_wlo1[256 * 256];
__device__ int   g_deg[NN];
__device__ int   g_rowptr[NN + 1];
__device__ int   g_wp[NN];
__device__ int   g_bsum[64];
__device__ int   g_csrc[EE];

__device__ __forceinline__ uint32_t s2u(const void* p) {
    uint32_t a;
    asm("{ .reg .u64 t; cvta.to.shared.u64 t, %1; cvt.u32.u64 %0, t; }" : "=r"(a) : "l"(p));
    return a;
}

// ---------------- per-branch arg bundles (passed by value) ----------------
struct GemmArgs {
    const __nv_bfloat16* Ahi[2];
    const __nv_bfloat16* Alo[2];
    const __nv_bfloat16* Bhi[2];
    const __nv_bfloat16* Blo[2];
    const float* al[2];
    const float* ar[2];
    float* C[2];
    float* el[2];
    float* er[2];
};
struct AggArgs {
    const float* el[2];
    const float* er[2];
    const float* feat[2];
    float* out[2];
    __nv_bfloat16* ohi[2];
    __nv_bfloat16* olo[2];
    int act[2];
};

// ================= CSR build =================
__global__ void zero_deg(int* deg, int N) {
    int i = blockIdx.x * blockDim.x + threadIdx.x;
    if (i < N) deg[i] = 0;
}
__global__ void hist_k(const int* __restrict__ dst, int* __restrict__ deg, int E) {
    int i = blockIdx.x * blockDim.x + threadIdx.x;
    if (i < E) atomicAdd(&deg[dst[i]], 1);
}
__global__ void scan_tiles(const int* __restrict__ deg, int* __restrict__ rowptr,
                           int* __restrict__ bsum, int N) {
    __shared__ int sh[1024];
    int i = blockIdx.x * 1024 + threadIdx.x;
    int v = (i < N) ? deg[i] : 0;
    sh[threadIdx.x] = v;
    __syncthreads();
    for (int o = 1; o < 1024; o <<= 1) {
        int t = (threadIdx.x >= o) ? sh[threadIdx.x - o] : 0;
        __syncthreads();
        sh[threadIdx.x] += t;
        __syncthreads();
    }
    if (i < N) rowptr[i] = sh[threadIdx.x] - v;
    if (threadIdx.x == 1023) bsum[blockIdx.x] = sh[1023];
}
__global__ void scan_bsum(int* bsum, int nb) {
    if (threadIdx.x == 0 && blockIdx.x == 0) {
        int acc = 0;
        for (int b = 0; b < nb; b++) { int t = bsum[b]; bsum[b] = acc; acc += t; }
    }
}
__global__ void add_off(int* __restrict__ rowptr, int* __restrict__ wp,
                        const int* __restrict__ bsum, int N, int E) {
    int i = blockIdx.x * blockDim.x + threadIdx.x;
    if (i < N) {
        int v = rowptr[i] + bsum[i >> 10];
        rowptr[i] = v;
        wp[i] = v;
    }
    if (i == 0) rowptr[N] = E;
}
__global__ void scatter_k(const int* __restrict__ src, const int* __restrict__ dst,
                          int* __restrict__ wp, int* __restrict__ csrc, int E) {
    int i = blockIdx.x * blockDim.x + threadIdx.x;
    if (i < E) {
        int pos = atomicAdd(&wp[dst[i]], 1);
        csrc[pos] = src[i];
    }
}

// ================= split / W-prep =================
__global__ void split_k(const float* __restrict__ v, __nv_bfloat16* __restrict__ hi,
                        __nv_bfloat16* __restrict__ lo, int n) {
    int i = blockIdx.x * blockDim.x + threadIdx.x;
    if (i < n) {
        float f = v[i];
        __nv_bfloat16 h = __float2bfloat16(f);
        hi[i] = h;
        lo[i] = __float2bfloat16(f - __bfloat162float(h));
    }
}
// batched over 2 branches via blockIdx.y
__global__ void prepw_k(const float* __restrict__ W0, const float* __restrict__ W1,
                        __nv_bfloat16* __restrict__ hi0, __nv_bfloat16* __restrict__ lo0,
                        __nv_bfloat16* __restrict__ hi1, __nv_bfloat16* __restrict__ lo1,
                        int K, int J, int J64) {
    int i = blockIdx.x * blockDim.x + threadIdx.x;
    const float* W = blockIdx.y ? W1 : W0;
    __nv_bfloat16* hi = blockIdx.y ? hi1 : hi0;
    __nv_bfloat16* lo = blockIdx.y ? lo1 : lo0;
    if (i < K * J64) {
        int j = i / K, k = i % K;
        float f = (j < J) ? W[k * J + j] : 0.f;
        __nv_bfloat16 h = __float2bfloat16(f);
        hi[i] = h;
        lo[i] = __float2bfloat16(f - __bfloat162float(h));
    }
}

// ================= mma.sync bf16 GEMM, ldmatrix, fused scores, batched z=2 ==========
#define MMA_BF16(d, a, b)                                                          \
    asm volatile(                                                                  \
        "mma.sync.aligned.m16n8k16.row.col.f32.bf16.bf16.f32 "                     \
        "{%0,%1,%2,%3},{%4,%5,%6,%7},{%8,%9},{%0,%1,%2,%3};"                       \
        : "+f"((d)[0]), "+f"((d)[1]), "+f"((d)[2]), "+f"((d)[3])                   \
        : "r"((a)[0]), "r"((a)[1]), "r"((a)[2]), "r"((a)[3]), "r"((b)[0]), "r"((b)[1]))
#define LDSM4(r, addr)                                                             \
    asm volatile("ldmatrix.sync.aligned.m8n8.x4.shared.b16 {%0,%1,%2,%3}, [%4];"   \
        : "=r"((r)[0]), "=r"((r)[1]), "=r"((r)[2]), "=r"((r)[3]) : "r"(addr))

template <int K, int J, int D>
__global__ __launch_bounds__(256) void gemm_mma(GemmArgs ga, int M) {
    constexpr int H = J / D;
    constexpr int BK = 32, STR = BK + 8;
    __shared__ __nv_bfloat16 sAh[128 * STR], sAl[128 * STR];
    __shared__ __nv_bfloat16 sBh[64 * STR], sBl[64 * STR];
    __shared__ float sEl[128][2], sEr[128][2];
    const int z = blockIdx.z;
    const __nv_bfloat16* __restrict__ Ahi = ga.Ahi[z];
    const __nv_bfloat16* __restrict__ Alo = ga.Alo[z];
    const __nv_bfloat16* __restrict__ Bhi = ga.Bhi[z];
    const __nv_bfloat16* __restrict__ Blo = ga.Blo[z];
    const float* __restrict__ alv = ga.al[z];
    const float* __restrict__ arv = ga.ar[z];
    float* __restrict__ C = ga.C[z];
    float* __restrict__ el = ga.el[z];
    float* __restrict__ er = ga.er[z];

    const int tid = threadIdx.x;
    const int wid = tid >> 5, lane = tid & 31;
    const int g = lane >> 2, t = lane & 3;
    const int wm = wid & 3, wn = wid >> 2;
    const int row0 = blockIdx.y * 128, col0 = blockIdx.x * 64;

    float acc[2][4][4];
#pragma unroll
    for (int am = 0; am < 2; am++)
#pragma unroll
        for (int an = 0; an < 4; an++)
#pragma unroll
            for (int q = 0; q < 4; q++) acc[am][an][q] = 0.f;

    uint4 rah[2], ral[2], rbh, rbl;
    const int ar0 = tid >> 2, acb0 = (tid & 3) * 8;
    const int ar1 = (tid + 256) >> 2, acb1 = ((tid + 256) & 3) * 8;
    const int gra0 = min(row0 + ar0, M - 1), gra1 = min(row0 + ar1, M - 1);
    const int brr = tid >> 2, bcb = (tid & 3) * 8;

#define LOADREG(kb)                                                                  \
    do {                                                                             \
        rah[0] = *(const uint4*)&Ahi[(size_t)gra0 * K + (kb) + acb0];                \
        ral[0] = *(const uint4*)&Alo[(size_t)gra0 * K + (kb) + acb0];                \
        rah[1] = *(const uint4*)&Ahi[(size_t)gra1 * K + (kb) + acb1];                \
        ral[1] = *(const uint4*)&Alo[(size_t)gra1 * K + (kb) + acb1];                \
        rbh = *(const uint4*)&Bhi[(size_t)(col0 + brr) * K + (kb) + bcb];            \
        rbl = *(const uint4*)&Blo[(size_t)(col0 + brr) * K + (kb) + bcb];            \
    } while (0)

    const uint32_t uAh = s2u(sAh), uAl = s2u(sAl), uBh = s2u(sBh), uBl = s2u(sBl);
    const int lar = ((lane >> 3) & 1) * 8 + (lane & 7);
    const int lak = (lane >> 4) * 8;
    const uint32_t aoff = (uint32_t)((lar * STR + lak) * 2);
    const uint32_t amo0 = (uint32_t)((wm * 32) * STR * 2);
    const uint32_t amo1 = amo0 + (uint32_t)(16 * STR * 2);
    const int bn = lane & 7, bk2 = ((lane >> 3) & 1) * 8, bsel = lane >> 4;
    uint32_t boff[2];
#pragma unroll
    for (int p = 0; p < 2; p++)
        boff[p] = (uint32_t)(((wn * 32 + (2 * p + bsel) * 8 + bn) * STR + bk2) * 2);

    LOADREG(0);
    for (int kb = 0; kb < K; kb += BK) {
        *(uint4*)&sAh[ar0 * STR + acb0] = rah[0];
        *(uint4*)&sAl[ar0 * STR + acb0] = ral[0];
        *(uint4*)&sAh[ar1 * STR + acb1] = rah[1];
        *(uint4*)&sAl[ar1 * STR + acb1] = ral[1];
        *(uint4*)&sBh[brr * STR + bcb] = rbh;
        *(uint4*)&sBl[brr * STR + bcb] = rbl;
        __syncthreads();
        if (kb + BK < K) LOADREG(kb + BK);
#pragma unroll
        for (int ks = 0; ks < BK / 16; ks++) {
            const uint32_t k2 = (uint32_t)(ks * 16 * 2);
            uint32_t ah[2][4], al_[2][4], bh[2][4], bl[2][4];
            LDSM4(ah[0], uAh + amo0 + aoff + k2);
            LDSM4(ah[1], uAh + amo1 + aoff + k2);
            LDSM4(al_[0], uAl + amo0 + aoff + k2);
            LDSM4(al_[1], uAl + amo1 + aoff + k2);
            LDSM4(bh[0], uBh + boff[0] + k2);
            LDSM4(bh[1], uBh + boff[1] + k2);
            LDSM4(bl[0], uBl + boff[0] + k2);
            LDSM4(bl[1], uBl + boff[1] + k2);
#pragma unroll
            for (int am = 0; am < 2; am++)
#pragma unroll
                for (int an = 0; an < 4; an++) {
                    uint32_t* bph = &bh[an >> 1][(an & 1) * 2];
                    uint32_t* bpl = &bl[an >> 1][(an & 1) * 2];
                    MMA_BF16(acc[am][an], ah[am], bph);
                    MMA_BF16(acc[am][an], ah[am], bpl);
                    MMA_BF16(acc[am][an], al_[am], bph);
                }
        }
        __syncthreads();
    }
#undef LOADREG

    // ---- store C + fused attention scores (smem cross-warp reduce, no atomics) ----
    const int head = (col0 + wn * 32) / D;
    float alc[4][2], arc[4][2];
#pragma unroll
    for (int an = 0; an < 4; an++) {
        int c = col0 + wn * 32 + an * 8 + 2 * t;
#pragma unroll
        for (int q = 0; q < 2; q++) {
            alc[an][q] = (c + q < J) ? __ldg(alv + c + q) : 0.f;
            arc[an][q] = (c + q < J) ? __ldg(arv + c + q) : 0.f;
        }
    }
#pragma unroll
    for (int am = 0; am < 2; am++) {
        int r0 = row0 + wm * 32 + am * 16 + g;
        float pl0 = 0.f, pr0 = 0.f, pl8 = 0.f, pr8 = 0.f;
#pragma unroll
        for (int an = 0; an < 4; an++) {
            int c = col0 + wn * 32 + an * 8 + 2 * t;
            if (c < J) {
                if (r0 < M)
                    *(float2*)&C[(size_t)r0 * J + c] = make_float2(acc[am][an][0], acc[am][an][1]);
                if (r0 + 8 < M)
                    *(float2*)&C[(size_t)(r0 + 8) * J + c] = make_float2(acc[am][an][2], acc[am][an][3]);
            }
            pl0 += acc[am][an][0] * alc[an][0] + acc[am][an][1] * alc[an][1];
            pr0 += acc[am][an][0] * arc[an][0] + acc[am][an][1] * arc[an][1];
            pl8 += acc[am][an][2] * alc[an][0] + acc[am][an][3] * alc[an][1];
            pr8 += acc[am][an][2] * arc[an][0] + acc[am][an][3] * arc[an][1];
        }
#pragma unroll
        for (int o = 1; o < 4; o <<= 1) {
            pl0 += __shfl_xor_sync(0xffffffffu, pl0, o);
            pr0 += __shfl_xor_sync(0xffffffffu, pr0, o);
            pl8 += __shfl_xor_sync(0xffffffffu, pl8, o);
            pr8 += __shfl_xor_sync(0xffffffffu, pr8, o);
        }
        if (t == 0) {
            int rl = wm * 32 + am * 16 + g;
            sEl[rl][wn] = pl0; sEr[rl][wn] = pr0;
            sEl[rl + 8][wn] = pl8; sEr[rl + 8][wn] = pr8;
        }
    }
    __syncthreads();
    if (tid < 128) {
        int row = row0 + tid;
        if (row < M) {
            el[row * H + head] = sEl[tid][0] + sEl[tid][1];
            er[row * H + head] = sEr[tid][0] + sEr[tid][1];
        }
    }
}

// ============ fused softmax + aggregate (CSR, one warp per node, batched y=2) ========
template <int H, int D, int WM>
__global__ __launch_bounds__(256) void agg_k(const int* __restrict__ rowptr,
                                             const int* __restrict__ csrc,
                                             AggArgs aa, int N) {
    constexpr int HD = H * D;
    const int z = blockIdx.y;
    const float* __restrict__ el = aa.el[z];
    const float* __restrict__ er = aa.er[z];
    const float* __restrict__ feat = aa.feat[z];
    float* __restrict__ out = aa.out[z];
    __nv_bfloat16* __restrict__ ohi = aa.ohi[z];
    __nv_bfloat16* __restrict__ olo = aa.olo[z];
    const int act = aa.act[z];

    int warp = (blockIdx.x * blockDim.x + threadIdx.x) >> 5;
    int lane = threadIdx.x & 31;
    if (warp >= N) return;
    int beg = rowptr[warp];
    int end = rowptr[warp + 1];

    float erh[H];
    if (H == 4) {
        float4 t = __ldg((const float4*)er + warp);
        erh[0] = t.x; erh[1] = t.y; erh[2] = t.z; erh[3] = t.w;
    } else {
        erh[0] = __ldg(er + warp);
    }

    float m[H], den[H];
#pragma unroll
    for (int h = 0; h < H; h++) { m[h] = -1e30f; den[h] = 0.f; }
    for (int j = beg + lane; j < end; j += 32) {
        int s = __ldg(csrc + j);
        float eh[H];
        if (H == 4) {
            float4 t = __ldg((const float4*)el + s);
            eh[0] = t.x; eh[1] = t.y; eh[2] = t.z; eh[3] = t.w;
        } else eh[0] = __ldg(el + s);
#pragma unroll
        for (int h = 0; h < H; h++) {
            float v = eh[h] + erh[h];
            v = (v > 0.f) ? v : 0.2f * v;
            float nm = fmaxf(m[h], v);
            den[h] = den[h] * __expf(m[h] - nm) + __expf(v - nm);
            m[h] = nm;
        }
    }
    float inv[H];
#pragma unroll
    for (int h = 0; h < H; h++) {
#pragma unroll
        for (int o = 16; o; o >>= 1) {
            float mo = __shfl_xor_sync(0xffffffffu, m[h], o);
            float dn = __shfl_xor_sync(0xffffffffu, den[h], o);
            float nm = fmaxf(m[h], mo);
            den[h] = den[h] * __expf(m[h] - nm) + dn * __expf(mo - nm);
            m[h] = nm;
        }
        inv[h] = 1.f / fmaxf(den[h], 1e-9f);
    }

    if (HD == 256) {
        const bool up = (lane & 16);
        const float m_a = up ? m[1] : m[0],  m_b = up ? m[3] : m[2];
        const float i_a = up ? inv[1] : inv[0], i_b = up ? inv[3] : inv[2];
        const float e_a = up ? erh[1] : erh[0], e_b = up ? erh[3] : erh[2];
        float4 acc0 = make_float4(0.f, 0.f, 0.f, 0.f);
        float4 acc1 = make_float4(0.f, 0.f, 0.f, 0.f);
        int j = beg;
        for (; j + 4 <= end; j += 4) {
            int s0 = __ldg(csrc + j), s1 = __ldg(csrc + j + 1);
            int s2 = __ldg(csrc + j + 2), s3 = __ldg(csrc + j + 3);
            const float4* fr0 = (const float4*)(feat + (size_t)s0 * 256);
            const float4* fr1 = (const float4*)(feat + (size_t)s1 * 256);
            const float4* fr2 = (const float4*)(feat + (size_t)s2 * 256);
            const float4* fr3 = (const float4*)(feat + (size_t)s3 * 256);
            float4 f00 = __ldg(fr0 + lane), f01 = __ldg(fr0 + 32 + lane);
            float4 f10 = __ldg(fr1 + lane), f11 = __ldg(fr1 + 32 + lane);
            float4 f20 = __ldg(fr2 + lane), f21 = __ldg(fr2 + 32 + lane);
            float4 f30 = __ldg(fr3 + lane), f31 = __ldg(fr3 + 32 + lane);
            float4 e40 = __ldg((const float4*)el + s0);
            float4 e41 = __ldg((const float4*)el + s1);
            float4 e42 = __ldg((const float4*)el + s2);
            float4 e43 = __ldg((const float4*)el + s3);
            float v0a = (up ? e40.y : e40.x) + e_a; v0a = (v0a > 0.f) ? v0a : 0.2f * v0a;
            float v0b = (up ? e40.w : e40.z) + e_b; v0b = (v0b > 0.f) ? v0b : 0.2f * v0b;
            float v1a = (up ? e41.y : e41.x) + e_a; v1a = (v1a > 0.f) ? v1a : 0.2f * v1a;
            float v1b = (up ? e41.w : e41.z) + e_b; v1b = (v1b > 0.f) ? v1b : 0.2f * v1b;
            float v2a = (up ? e42.y : e42.x) + e_a; v2a = (v2a > 0.f) ? v2a : 0.2f * v2a;
            float v2b = (up ? e42.w : e42.z) + e_b; v2b = (v2b > 0.f) ? v2b : 0.2f * v2b;
            float v3a = (up ? e43.y : e43.x) + e_a; v3a = (v3a > 0.f) ? v3a : 0.2f * v3a;
            float v3b = (up ? e43.w : e43.z) + e_b; v3b = (v3b > 0.f) ? v3b : 0.2f * v3b;
            float a0a = __expf(v0a - m_a) * i_a, a0b = __expf(v0b - m_b) * i_b;
            float a1a = __expf(v1a - m_a) * i_a, a1b = __expf(v1b - m_b) * i_b;
            float a2a = __expf(v2a - m_a) * i_a, a2b = __expf(v2b - m_b) * i_b;
            float a3a = __expf(v3a - m_a) * i_a, a3b = __expf(v3b - m_b) * i_b;
            acc0.x += f00.x * a0a + f10.x * a1a + f20.x * a2a + f30.x * a3a;
            acc0.y += f00.y * a0a + f10.y * a1a + f20.y * a2a + f30.y * a3a;
            acc0.z += f00.z * a0a + f10.z * a1a + f20.z * a2a + f30.z * a3a;
            acc0.w += f00.w * a0a + f10.w * a1a + f20.w * a2a + f30.w * a3a;
            acc1.x += f01.x * a0b + f11.x * a1b + f21.x * a2b + f31.x * a3b;
            acc1.y += f01.y * a0b + f11.y * a1b + f21.y * a2b + f31.y * a3b;
            acc1.z += f01.z * a0b + f11.z * a1b + f21.z * a2b + f31.z * a3b;
            acc1.w += f01.w * a0b + f11.w * a1b + f21.w * a2b + f31.w * a3b;
        }
        for (; j < end; j++) {
            int s0 = __ldg(csrc + j);
            const float4* fr0 = (const float4*)(feat + (size_t)s0 * 256);
            float4 f00 = __ldg(fr0 + lane), f01 = __ldg(fr0 + 32 + lane);
            float4 e40 = __ldg((const float4*)el + s0);
            float v0a = (up ? e40.y : e40.x) + e_a; v0a = (v0a > 0.f) ? v0a : 0.2f * v0a;
            float v0b = (up ? e40.w : e40.z) + e_b; v0b = (v0b > 0.f) ? v0b : 0.2f * v0b;
            float a0a = __expf(v0a - m_a) * i_a, a0b = __expf(v0b - m_b) * i_b;
            acc0.x += f00.x * a0a; acc0.y += f00.y * a0a; acc0.z += f00.z * a0a; acc0.w += f00.w * a0a;
            acc1.x += f01.x * a0b; acc1.y += f01.y * a0b; acc1.z += f01.z * a0b; acc1.w += f01.w * a0b;
        }
#pragma unroll
        for (int q = 0; q < 2; q++) {
            float4 v = q ? acc1 : acc0;
            if (act) {
                v.x = (v.x > 0.f) ? v.x : expm1f(v.x);
                v.y = (v.y > 0.f) ? v.y : expm1f(v.y);
                v.z = (v.z > 0.f) ? v.z : expm1f(v.z);
                v.w = (v.w > 0.f) ? v.w : expm1f(v.w);
            }
            size_t idx = (size_t)warp * 256 + q * 128 + lane * 4;
            if (WM == 0) {
                *(float4*)(out + idx) = v;
            } else {
                __nv_bfloat16 hx = __float2bfloat16(v.x), hy = __float2bfloat16(v.y);
                __nv_bfloat16 hz = __float2bfloat16(v.z), hw = __float2bfloat16(v.w);
                __nv_bfloat162* ph = (__nv_bfloat162*)(ohi + idx);
                __nv_bfloat162* pl = (__nv_bfloat162*)(olo + idx);
                ph[0] = __nv_bfloat162(hx, hy);
                ph[1] = __nv_bfloat162(hz, hw);
                pl[0] = __nv_bfloat162(__float2bfloat16(v.x - __bfloat162float(hx)),
                                       __float2bfloat16(v.y - __bfloat162float(hy)));
                pl[1] = __nv_bfloat162(__float2bfloat16(v.z - __bfloat162float(hz)),
                                       __float2bfloat16(v.w - __bfloat162float(hw)));
            }
        }
    } else {
        // H==1: two 16-lane gangs, 4-edge unroll per gang
        constexpr int NV = HD / 4;
        const int gp = lane >> 4, gl = lane & 15;
        const float m0 = m[0], i0 = inv[0], e0 = erh[0];
        float4 acc = make_float4(0.f, 0.f, 0.f, 0.f);
        int j = beg + gp;
        for (; j + 6 < end; j += 8) {
            int s0 = __ldg(csrc + j),     s1 = __ldg(csrc + j + 2);
            int s2 = __ldg(csrc + j + 4), s3 = __ldg(csrc + j + 6);
            float el0 = __ldg(el + s0), el1 = __ldg(el + s1);
            float el2 = __ldg(el + s2), el3 = __ldg(el + s3);
            float4 f0 = make_float4(0.f, 0.f, 0.f, 0.f), f1 = f0, f2 = f0, f3 = f0;
            if (gl < NV) {
                f0 = __ldg((const float4*)(feat + (size_t)s0 * HD) + gl);
                f1 = __ldg((const float4*)(feat + (size_t)s1 * HD) + gl);
                f2 = __ldg((const float4*)(feat + (size_t)s2 * HD) + gl);
                f3 = __ldg((const float4*)(feat + (size_t)s3 * HD) + gl);
            }
            float v0 = el0 + e0; v0 = (v0 > 0.f) ? v0 : 0.2f * v0;
            float v1 = el1 + e0; v1 = (v1 > 0.f) ? v1 : 0.2f * v1;
            float v2 = el2 + e0; v2 = (v2 > 0.f) ? v2 : 0.2f * v2;
            float v3 = el3 + e0; v3 = (v3 > 0.f) ? v3 : 0.2f * v3;
            float a0 = __expf(v0 - m0) * i0, a1 = __expf(v1 - m0) * i0;
            float a2 = __expf(v2 - m0) * i0, a3 = __expf(v3 - m0) * i0;
            acc.x += f0.x * a0 + f1.x * a1 + f2.x * a2 + f3.x * a3;
            acc.y += f0.y * a0 + f1.y * a1 + f2.y * a2 + f3.y * a3;
            acc.z += f0.z * a0 + f1.z * a1 + f2.z * a2 + f3.z * a3;
            acc.w += f0.w * a0 + f1.w * a1 + f2.w * a2 + f3.w * a3;
        }
        for (; j < end; j += 2) {
            int s0 = __ldg(csrc + j);
            float el0 = __ldg(el + s0);
            float4 f0 = make_float4(0.f, 0.f, 0.f, 0.f);
            if (gl < NV) f0 = __ldg((const float4*)(feat + (size_t)s0 * HD) + gl);
            float v0 = el0 + e0; v0 = (v0 > 0.f) ? v0 : 0.2f * v0;
            float a0 = __expf(v0 - m0) * i0;
            acc.x += f0.x * a0; acc.y += f0.y * a0; acc.z += f0.z * a0; acc.w += f0.w * a0;
        }
        acc.x += __shfl_xor_sync(0xffffffffu, acc.x, 16);
        acc.y += __shfl_xor_sync(0xffffffffu, acc.y, 16);
        acc.z += __shfl_xor_sync(0xffffffffu, acc.z, 16);
        acc.w += __shfl_xor_sync(0xffffffffu, acc.w, 16);
        if (lane < NV) {
            if (act) {
                acc.x = (acc.x > 0.f) ? acc.x : expm1f(acc.x);
                acc.y = (acc.y > 0.f) ? acc.y : expm1f(acc.y);
                acc.z = (acc.z > 0.f) ? acc.z : expm1f(acc.z);
                acc.w = (acc.w > 0.f) ? acc.w : expm1f(acc.w);
            }
            size_t idx = (size_t)warp * HD + lane * 4;
            if (WM == 0) {
                *(float4*)(out + idx) = acc;
            } else {
                __nv_bfloat16 hx = __float2bfloat16(acc.x), hy = __float2bfloat16(acc.y);
                __nv_bfloat16 hz = __float2bfloat16(acc.z), hw = __float2bfloat16(acc.w);
                __nv_bfloat162* ph = (__nv_bfloat162*)(ohi + idx);
                __nv_bfloat162* pl = (__nv_bfloat162*)(olo + idx);
                ph[0] = __nv_bfloat162(hx, hy);
                ph[1] = __nv_bfloat162(hz, hw);
                pl[0] = __nv_bfloat162(__float2bfloat16(acc.x - __bfloat162float(hx)),
                                       __float2bfloat16(acc.y - __bfloat162float(hy)));
                pl[1] = __nv_bfloat162(__float2bfloat16(acc.z - __bfloat162float(hz)),
                                       __float2bfloat16(acc.w - __bfloat162float(hw)));
            }
        }
    }
}

extern "C" void kernel_launch(void* const* d_in, const int* in_sizes, int n_in,
                              void* d_out, int out_size) {
    const float* x    = (const float*)d_in[0];
    const int*   src  = (const int*)d_in[1];
    const int*   dst  = (const int*)d_in[2];
    const float* W00  = (const float*)d_in[3];
    const float* a00l = (const float*)d_in[4];
    const float* a00r = (const float*)d_in[5];
    const float* W01  = (const float*)d_in[6];
    const float* a01l = (const float*)d_in[7];
    const float* a01r = (const float*)d_in[8];
    const float* W0f  = (const float*)d_in[9];
    const float* a0fl = (const float*)d_in[10];
    const float* a0fr = (const float*)d_in[11];
    const float* W10  = (const float*)d_in[12];
    const float* a10l = (const float*)d_in[13];
    const float* a10r = (const float*)d_in[14];
    const float* W1f  = (const float*)d_in[15];
    const float* a1fl = (const float*)d_in[16];
    const float* a1fr = (const float*)d_in[17];
    const float* W1o  = (const float*)d_in[18];
    const float* a1ol = (const float*)d_in[19];
    const float* a1or = (const float*)d_in[20];
    float* out = (float*)d_out;

    const int N = in_sizes[0] / 256;
    const int E = in_sizes[1];

    float *feat0, *feat1, *el0, *er0, *el1, *er1;
    __nv_bfloat16 *xhi, *xlo, *hhi0, *hlo0, *hhi1, *hlo1, *whi0, *wlo0, *whi1, *wlo1;
    int *deg, *rowptr, *wp, *bsum, *csrc;
    cudaGetSymbolAddress((void**)&feat0, g_feat0);
    cudaGetSymbolAddress((void**)&feat1, g_feat1);
    cudaGetSymbolAddress((void**)&el0, g_el0);
    cudaGetSymbolAddress((void**)&er0, g_er0);
    cudaGetSymbolAddress((void**)&el1, g_el1);
    cudaGetSymbolAddress((void**)&er1, g_er1);
    cudaGetSymbolAddress((void**)&xhi, g_xhi);
    cudaGetSymbolAddress((void**)&xlo, g_xlo);
    cudaGetSymbolAddress((void**)&hhi0, g_hhi0);
    cudaGetSymbolAddress((void**)&hlo0, g_hlo0);
    cudaGetSymbolAddress((void**)&hhi1, g_hhi1);
    cudaGetSymbolAddress((void**)&hlo1, g_hlo1);
    cudaGetSymbolAddress((void**)&whi0, g_whi0);
    cudaGetSymbolAddress((void**)&wlo0, g_wlo0);
    cudaGetSymbolAddress((void**)&whi1, g_whi1);
    cudaGetSymbolAddress((void**)&wlo1, g_wlo1);
    cudaGetSymbolAddress((void**)&deg, g_deg);
    cudaGetSymbolAddress((void**)&rowptr, g_rowptr);
    cudaGetSymbolAddress((void**)&wp, g_wp);
    cudaGetSymbolAddress((void**)&bsum, g_bsum);
    cudaGetSymbolAddress((void**)&csrc, g_csrc);

    // ---- prelude: x split + CSR build (default stream) ----
    split_k<<<((long)N * 256 + 255) / 256, 256>>>(x, xhi, xlo, N * 256);
    zero_deg<<<(N + 255) / 256, 256>>>(deg, N);
    hist_k<<<(E + 255) / 256, 256>>>(dst, deg, E);
    int ntiles = (N + 1023) / 1024;
    scan_tiles<<<ntiles, 1024>>>(deg, rowptr, bsum, N);
    scan_bsum<<<1, 32>>>(bsum, ntiles);
    add_off<<<(N + 255) / 256, 256>>>(rowptr, wp, bsum, N, E);
    scatter_k<<<(E + 255) / 256, 256>>>(src, dst, wp, csrc, E);

    const int aggGridX = (N * 32 + 255) / 256;

    // ================= layer 1 (both branches, H=4, K=256, J=256) =================
    {
        prepw_k<<<dim3((256 * 256 + 255) / 256, 2), 256>>>(W00, W10, whi0, wlo0, whi1, wlo1,
                                                           256, 256, 256);
        GemmArgs ga = {};
        ga.Ahi[0] = xhi;  ga.Alo[0] = xlo;  ga.Ahi[1] = xhi;  ga.Alo[1] = xlo;
        ga.Bhi[0] = whi0; ga.Blo[0] = wlo0; ga.Bhi[1] = whi1; ga.Blo[1] = wlo1;
        ga.al[0] = a00l; ga.ar[0] = a00r; ga.al[1] = a10l; ga.ar[1] = a10r;
        ga.C[0] = feat0; ga.el[0] = el0; ga.er[0] = er0;
        ga.C[1] = feat1; ga.el[1] = el1; ga.er[1] = er1;
        gemm_mma<256, 256, 64><<<dim3(4, (N + 127) / 128, 2), 256>>>(ga, N);
        AggArgs aa = {};
        aa.el[0] = el0; aa.er[0] = er0; aa.feat[0] = feat0;
        aa.ohi[0] = hhi0; aa.olo[0] = hlo0; aa.act[0] = 1;
        aa.el[1] = el1; aa.er[1] = er1; aa.feat[1] = feat1;
        aa.ohi[1] = hhi1; aa.olo[1] = hlo1; aa.act[1] = 1;
        agg_k<4, 64, 1><<<dim3(aggGridX, 2), 256>>>(rowptr, csrc, aa, N);
    }

    // ================= layer 2 (H=1, K=256, J=64; act: b0=elu, b1=none) ============
    {
        prepw_k<<<dim3((256 * 64 + 255) / 256, 2), 256>>>(W01, W1f, whi0, wlo0, whi1, wlo1,
                                                          256, 64, 64);
        GemmArgs ga = {};
        ga.Ahi[0] = hhi0; ga.Alo[0] = hlo0; ga.Ahi[1] = hhi1; ga.Alo[1] = hlo1;
        ga.Bhi[0] = whi0; ga.Blo[0] = wlo0; ga.Bhi[1] = whi1; ga.Blo[1] = wlo1;
        ga.al[0] = a01l; ga.ar[0] = a01r; ga.al[1] = a1fl; ga.ar[1] = a1fr;
        ga.C[0] = feat0; ga.el[0] = el0; ga.er[0] = er0;
        ga.C[1] = feat1; ga.el[1] = el1; ga.er[1] = er1;
        gemm_mma<256, 64, 64><<<dim3(1, (N + 127) / 128, 2), 256>>>(ga, N);
        AggArgs aa = {};
        aa.el[0] = el0; aa.er[0] = er0; aa.feat[0] = feat0;
        aa.ohi[0] = hhi0; aa.olo[0] = hlo0; aa.act[0] = 1;
        aa.el[1] = el1; aa.er[1] = er1; aa.feat[1] = feat1;
        aa.ohi[1] = hhi1; aa.olo[1] = hlo1; aa.act[1] = 0;
        agg_k<1, 64, 1><<<dim3(aggGridX, 2), 256>>>(rowptr, csrc, aa, N);
    }

    // ================= layer 3 (H=1, K=64, J=40; act: b0=none, b1=elu) =============
    {
        prepw_k<<<dim3((64 * 64 + 255) / 256, 2), 256>>>(W0f, W1o, whi0, wlo0, whi1, wlo1,
                                                         64, 40, 64);
        GemmArgs ga = {};
        ga.Ahi[0] = hhi0; ga.Alo[0] = hlo0; ga.Ahi[1] = hhi1; ga.Alo[1] = hlo1;
        ga.Bhi[0] = whi0; ga.Blo[0] = wlo0; ga.Bhi[1] = whi1; ga.Blo[1] = wlo1;
        ga.al[0] = a0fl; ga.ar[0] = a0fr; ga.al[1] = a1ol; ga.ar[1] = a1or;
        ga.C[0] = feat0; ga.el[0] = el0; ga.er[0] = er0;
        ga.C[1] = feat1; ga.el[1] = el1; ga.er[1] = er1;
        gemm_mma<64, 40, 40><<<dim3(1, (N + 127) / 128, 2), 256>>>(ga, N);
        AggArgs aa = {};
        aa.el[0] = el0; aa.er[0] = er0; aa.feat[0] = feat0;
        aa.out[0] = out; aa.act[0] = 0;
        aa.el[1] = el1; aa.er[1] = er1; aa.feat[1] = feat1;
        aa.out[1] = out + (size_t)N * CC; aa.act[1] = 1;
        agg_k<1, 40, 0><<<dim3(aggGridX, 2), 256>>>(rowptr, csrc, aa, N);
    }
}

// round 16
// speedup vs baseline: 1.4059x; 1.4059x over previous
#include <cuda_runtime.h>
#include <cuda_bf16.h>
#include <math.h>
#include <stdint.h>

#define NN 50000
#define EE 800000
#define CC 40

// ---------------- scratch (device globals; no allocations allowed) ----------------
__device__ __align__(16) float g_feat0[NN * 256];
__device__ __align__(16) float g_feat1[NN * 256];
__device__ __align__(16) float g_el0[NN * 4];
__device__ __align__(16) float g_er0[NN * 4];
__device__ __align__(16) float g_el1[NN * 4];
__device__ __align__(16) float g_er1[NN * 4];
__device__ __align__(16) __nv_bfloat16 g_xhi[NN * 256];
__device__ __align__(16) __nv_bfloat16 g_xlo[NN * 256];
__device__ __align__(16) __nv_bfloat16 g_hhi0[NN * 256];
__device__ __align__(16) __nv_bfloat16 g_hlo0[NN * 256];
__device__ __align__(16) __nv_bfloat16 g_hhi1[NN * 256];
__device__ __align__(16) __nv_bfloat16 g_hlo1[NN * 256];
__device__ __align__(16) __nv_bfloat16 g_whi0[256 * 256];
__device__ __align__(16) __nv_bfloat16 g_wlo0[256 * 256];
__device__ __align__(16) __nv_bfloat16 g_whi1[256 * 256];
__device__ __align__(16) __nv_bfloat16 g_wlo1[256 * 256];
__device__ int   g_deg[NN];
__device__ int   g_rowptr[NN + 1];
__device__ int   g_wp[NN];
__device__ int   g_bsum[64];
__device__ int   g_csrc[EE];

__device__ __forceinline__ uint32_t s2u(const void* p) {
    uint32_t a;
    asm("{ .reg .u64 t; cvta.to.shared.u64 t, %1; cvt.u32.u64 %0, t; }" : "=r"(a) : "l"(p));
    return a;
}

// ---------------- per-branch arg bundles (passed by value) ----------------
struct GemmArgs {
    const __nv_bfloat16* Ahi[2];
    const __nv_bfloat16* Alo[2];
    const __nv_bfloat16* Bhi[2];
    const __nv_bfloat16* Blo[2];
    const float* al[2];
    const float* ar[2];
    float* C[2];
    float* el[2];
    float* er[2];
};
struct AggArgs {
    const float* el[2];
    const float* er[2];
    const float* feat[2];
    float* out[2];
    __nv_bfloat16* ohi[2];
    __nv_bfloat16* olo[2];
    int act[2];
};

// ================= CSR build =================
__global__ void zero_deg(int* deg, int N) {
    int i = blockIdx.x * blockDim.x + threadIdx.x;
    if (i < N) deg[i] = 0;
}
__global__ void hist_k(const int* __restrict__ dst, int* __restrict__ deg, int E) {
    int i = blockIdx.x * blockDim.x + threadIdx.x;
    if (i < E) atomicAdd(&deg[dst[i]], 1);
}
__global__ void scan_tiles(const int* __restrict__ deg, int* __restrict__ rowptr,
                           int* __restrict__ bsum, int N) {
    __shared__ int sh[1024];
    int i = blockIdx.x * 1024 + threadIdx.x;
    int v = (i < N) ? deg[i] : 0;
    sh[threadIdx.x] = v;
    __syncthreads();
    for (int o = 1; o < 1024; o <<= 1) {
        int t = (threadIdx.x >= o) ? sh[threadIdx.x - o] : 0;
        __syncthreads();
        sh[threadIdx.x] += t;
        __syncthreads();
    }
    if (i < N) rowptr[i] = sh[threadIdx.x] - v;
    if (threadIdx.x == 1023) bsum[blockIdx.x] = sh[1023];
}
__global__ void scan_bsum(int* bsum, int nb) {
    if (threadIdx.x == 0 && blockIdx.x == 0) {
        int acc = 0;
        for (int b = 0; b < nb; b++) { int t = bsum[b]; bsum[b] = acc; acc += t; }
    }
}
__global__ void add_off(int* __restrict__ rowptr, int* __restrict__ wp,
                        const int* __restrict__ bsum, int N, int E) {
    int i = blockIdx.x * blockDim.x + threadIdx.x;
    if (i < N) {
        int v = rowptr[i] + bsum[i >> 10];
        rowptr[i] = v;
        wp[i] = v;
    }
    if (i == 0) rowptr[N] = E;
}
__global__ void scatter_k(const int* __restrict__ src, const int* __restrict__ dst,
                          int* __restrict__ wp, int* __restrict__ csrc, int E) {
    int i = blockIdx.x * blockDim.x + threadIdx.x;
    if (i < E) {
        int pos = atomicAdd(&wp[dst[i]], 1);
        csrc[pos] = src[i];
    }
}

// ================= split / W-prep =================
__global__ void split_k(const float* __restrict__ v, __nv_bfloat16* __restrict__ hi,
                        __nv_bfloat16* __restrict__ lo, int n) {
    int i = blockIdx.x * blockDim.x + threadIdx.x;
    if (i < n) {
        float f = v[i];
        __nv_bfloat16 h = __float2bfloat16(f);
        hi[i] = h;
        lo[i] = __float2bfloat16(f - __bfloat162float(h));
    }
}
// batched over 2 branches via blockIdx.y
__global__ void prepw_k(const float* __restrict__ W0, const float* __restrict__ W1,
                        __nv_bfloat16* __restrict__ hi0, __nv_bfloat16* __restrict__ lo0,
                        __nv_bfloat16* __restrict__ hi1, __nv_bfloat16* __restrict__ lo1,
                        int K, int J, int J64) {
    int i = blockIdx.x * blockDim.x + threadIdx.x;
    const float* W = blockIdx.y ? W1 : W0;
    __nv_bfloat16* hi = blockIdx.y ? hi1 : hi0;
    __nv_bfloat16* lo = blockIdx.y ? lo1 : lo0;
    if (i < K * J64) {
        int j = i / K, k = i % K;
        float f = (j < J) ? W[k * J + j] : 0.f;
        __nv_bfloat16 h = __float2bfloat16(f);
        hi[i] = h;
        lo[i] = __float2bfloat16(f - __bfloat162float(h));
    }
}

// ================= mma.sync bf16 GEMM, ldmatrix, fused scores, batched z ==========
#define MMA_BF16(d, a, b)                                                          \
    asm volatile(                                                                  \
        "mma.sync.aligned.m16n8k16.row.col.f32.bf16.bf16.f32 "                     \
        "{%0,%1,%2,%3},{%4,%5,%6,%7},{%8,%9},{%0,%1,%2,%3};"                       \
        : "+f"((d)[0]), "+f"((d)[1]), "+f"((d)[2]), "+f"((d)[3])                   \
        : "r"((a)[0]), "r"((a)[1]), "r"((a)[2]), "r"((a)[3]), "r"((b)[0]), "r"((b)[1]))
#define LDSM4(r, addr)                                                             \
    asm volatile("ldmatrix.sync.aligned.m8n8.x4.shared.b16 {%0,%1,%2,%3}, [%4];"   \
        : "=r"((r)[0]), "=r"((r)[1]), "=r"((r)[2]), "=r"((r)[3]) : "r"(addr))

template <int K, int J, int D>
__global__ __launch_bounds__(256) void gemm_mma(GemmArgs ga, int M) {
    constexpr int H = J / D;
    constexpr int BK = 32, STR = BK + 8;
    __shared__ __nv_bfloat16 sAh[128 * STR], sAl[128 * STR];
    __shared__ __nv_bfloat16 sBh[64 * STR], sBl[64 * STR];
    __shared__ float sEl[128][2], sEr[128][2];
    const int z = blockIdx.z;
    const __nv_bfloat16* __restrict__ Ahi = ga.Ahi[z];
    const __nv_bfloat16* __restrict__ Alo = ga.Alo[z];
    const __nv_bfloat16* __restrict__ Bhi = ga.Bhi[z];
    const __nv_bfloat16* __restrict__ Blo = ga.Blo[z];
    const float* __restrict__ alv = ga.al[z];
    const float* __restrict__ arv = ga.ar[z];
    float* __restrict__ C = ga.C[z];
    float* __restrict__ el = ga.el[z];
    float* __restrict__ er = ga.er[z];

    const int tid = threadIdx.x;
    const int wid = tid >> 5, lane = tid & 31;
    const int g = lane >> 2, t = lane & 3;
    const int wm = wid & 3, wn = wid >> 2;
    const int row0 = blockIdx.y * 128, col0 = blockIdx.x * 64;

    float acc[2][4][4];
#pragma unroll
    for (int am = 0; am < 2; am++)
#pragma unroll
        for (int an = 0; an < 4; an++)
#pragma unroll
            for (int q = 0; q < 4; q++) acc[am][an][q] = 0.f;

    uint4 rah[2], ral[2], rbh, rbl;
    const int ar0 = tid >> 2, acb0 = (tid & 3) * 8;
    const int ar1 = (tid + 256) >> 2, acb1 = ((tid + 256) & 3) * 8;
    const int gra0 = min(row0 + ar0, M - 1), gra1 = min(row0 + ar1, M - 1);
    const int brr = tid >> 2, bcb = (tid & 3) * 8;

#define LOADREG(kb)                                                                  \
    do {                                                                             \
        rah[0] = *(const uint4*)&Ahi[(size_t)gra0 * K + (kb) + acb0];                \
        ral[0] = *(const uint4*)&Alo[(size_t)gra0 * K + (kb) + acb0];                \
        rah[1] = *(const uint4*)&Ahi[(size_t)gra1 * K + (kb) + acb1];                \
        ral[1] = *(const uint4*)&Alo[(size_t)gra1 * K + (kb) + acb1];                \
        rbh = *(const uint4*)&Bhi[(size_t)(col0 + brr) * K + (kb) + bcb];            \
        rbl = *(const uint4*)&Blo[(size_t)(col0 + brr) * K + (kb) + bcb];            \
    } while (0)

    const uint32_t uAh = s2u(sAh), uAl = s2u(sAl), uBh = s2u(sBh), uBl = s2u(sBl);
    const int lar = ((lane >> 3) & 1) * 8 + (lane & 7);
    const int lak = (lane >> 4) * 8;
    const uint32_t aoff = (uint32_t)((lar * STR + lak) * 2);
    const uint32_t amo0 = (uint32_t)((wm * 32) * STR * 2);
    const uint32_t amo1 = amo0 + (uint32_t)(16 * STR * 2);
    const int bn = lane & 7, bk2 = ((lane >> 3) & 1) * 8, bsel = lane >> 4;
    uint32_t boff[2];
#pragma unroll
    for (int p = 0; p < 2; p++)
        boff[p] = (uint32_t)(((wn * 32 + (2 * p + bsel) * 8 + bn) * STR + bk2) * 2);

    LOADREG(0);
    for (int kb = 0; kb < K; kb += BK) {
        *(uint4*)&sAh[ar0 * STR + acb0] = rah[0];
        *(uint4*)&sAl[ar0 * STR + acb0] = ral[0];
        *(uint4*)&sAh[ar1 * STR + acb1] = rah[1];
        *(uint4*)&sAl[ar1 * STR + acb1] = ral[1];
        *(uint4*)&sBh[brr * STR + bcb] = rbh;
        *(uint4*)&sBl[brr * STR + bcb] = rbl;
        __syncthreads();
        if (kb + BK < K) LOADREG(kb + BK);
#pragma unroll
        for (int ks = 0; ks < BK / 16; ks++) {
            const uint32_t k2 = (uint32_t)(ks * 16 * 2);
            uint32_t ah[2][4], al_[2][4], bh[2][4], bl[2][4];
            LDSM4(ah[0], uAh + amo0 + aoff + k2);
            LDSM4(ah[1], uAh + amo1 + aoff + k2);
            LDSM4(al_[0], uAl + amo0 + aoff + k2);
            LDSM4(al_[1], uAl + amo1 + aoff + k2);
            LDSM4(bh[0], uBh + boff[0] + k2);
            LDSM4(bh[1], uBh + boff[1] + k2);
            LDSM4(bl[0], uBl + boff[0] + k2);
            LDSM4(bl[1], uBl + boff[1] + k2);
#pragma unroll
            for (int am = 0; am < 2; am++)
#pragma unroll
                for (int an = 0; an < 4; an++) {
                    uint32_t* bph = &bh[an >> 1][(an & 1) * 2];
                    uint32_t* bpl = &bl[an >> 1][(an & 1) * 2];
                    MMA_BF16(acc[am][an], ah[am], bph);
                    MMA_BF16(acc[am][an], ah[am], bpl);
                    MMA_BF16(acc[am][an], al_[am], bph);
                }
        }
        __syncthreads();
    }
#undef LOADREG

    // ---- store C + fused attention scores (smem cross-warp reduce, no atomics) ----
    const int head = (col0 + wn * 32) / D;
    float alc[4][2], arc[4][2];
#pragma unroll
    for (int an = 0; an < 4; an++) {
        int c = col0 + wn * 32 + an * 8 + 2 * t;
#pragma unroll
        for (int q = 0; q < 2; q++) {
            alc[an][q] = (c + q < J) ? __ldg(alv + c + q) : 0.f;
            arc[an][q] = (c + q < J) ? __ldg(arv + c + q) : 0.f;
        }
    }
#pragma unroll
    for (int am = 0; am < 2; am++) {
        int r0 = row0 + wm * 32 + am * 16 + g;
        float pl0 = 0.f, pr0 = 0.f, pl8 = 0.f, pr8 = 0.f;
#pragma unroll
        for (int an = 0; an < 4; an++) {
            int c = col0 + wn * 32 + an * 8 + 2 * t;
            if (c < J) {
                if (r0 < M)
                    *(float2*)&C[(size_t)r0 * J + c] = make_float2(acc[am][an][0], acc[am][an][1]);
                if (r0 + 8 < M)
                    *(float2*)&C[(size_t)(r0 + 8) * J + c] = make_float2(acc[am][an][2], acc[am][an][3]);
            }
            pl0 += acc[am][an][0] * alc[an][0] + acc[am][an][1] * alc[an][1];
            pr0 += acc[am][an][0] * arc[an][0] + acc[am][an][1] * arc[an][1];
            pl8 += acc[am][an][2] * alc[an][0] + acc[am][an][3] * alc[an][1];
            pr8 += acc[am][an][2] * arc[an][0] + acc[am][an][3] * arc[an][1];
        }
#pragma unroll
        for (int o = 1; o < 4; o <<= 1) {
            pl0 += __shfl_xor_sync(0xffffffffu, pl0, o);
            pr0 += __shfl_xor_sync(0xffffffffu, pr0, o);
            pl8 += __shfl_xor_sync(0xffffffffu, pl8, o);
            pr8 += __shfl_xor_sync(0xffffffffu, pr8, o);
        }
        if (t == 0) {
            int rl = wm * 32 + am * 16 + g;
            sEl[rl][wn] = pl0; sEr[rl][wn] = pr0;
            sEl[rl + 8][wn] = pl8; sEr[rl + 8][wn] = pr8;
        }
    }
    __syncthreads();
    if (tid < 128) {
        int row = row0 + tid;
        if (row < M) {
            el[row * H + head] = sEl[tid][0] + sEl[tid][1];
            er[row * H + head] = sEr[tid][0] + sEr[tid][1];
        }
    }
}

// ============ fused softmax + aggregate (CSR, one warp per node, batched y) ========
template <int H, int D, int WM>
__global__ __launch_bounds__(256) void agg_k(const int* __restrict__ rowptr,
                                             const int* __restrict__ csrc,
                                             AggArgs aa, int N) {
    constexpr int HD = H * D;
    const int z = blockIdx.y;
    const float* __restrict__ el = aa.el[z];
    const float* __restrict__ er = aa.er[z];
    const float* __restrict__ feat = aa.feat[z];
    float* __restrict__ out = aa.out[z];
    __nv_bfloat16* __restrict__ ohi = aa.ohi[z];
    __nv_bfloat16* __restrict__ olo = aa.olo[z];
    const int act = aa.act[z];

    int warp = (blockIdx.x * blockDim.x + threadIdx.x) >> 5;
    int lane = threadIdx.x & 31;
    if (warp >= N) return;
    int beg = rowptr[warp];
    int end = rowptr[warp + 1];

    float erh[H];
    if (H == 4) {
        float4 t = __ldg((const float4*)er + warp);
        erh[0] = t.x; erh[1] = t.y; erh[2] = t.z; erh[3] = t.w;
    } else {
        erh[0] = __ldg(er + warp);
    }

    float m[H], den[H];
#pragma unroll
    for (int h = 0; h < H; h++) { m[h] = -1e30f; den[h] = 0.f; }
    for (int j = beg + lane; j < end; j += 32) {
        int s = __ldg(csrc + j);
        float eh[H];
        if (H == 4) {
            float4 t = __ldg((const float4*)el + s);
            eh[0] = t.x; eh[1] = t.y; eh[2] = t.z; eh[3] = t.w;
        } else eh[0] = __ldg(el + s);
#pragma unroll
        for (int h = 0; h < H; h++) {
            float v = eh[h] + erh[h];
            v = (v > 0.f) ? v : 0.2f * v;
            float nm = fmaxf(m[h], v);
            den[h] = den[h] * __expf(m[h] - nm) + __expf(v - nm);
            m[h] = nm;
        }
    }
    float inv[H];
#pragma unroll
    for (int h = 0; h < H; h++) {
#pragma unroll
        for (int o = 16; o; o >>= 1) {
            float mo = __shfl_xor_sync(0xffffffffu, m[h], o);
            float dn = __shfl_xor_sync(0xffffffffu, den[h], o);
            float nm = fmaxf(m[h], mo);
            den[h] = den[h] * __expf(m[h] - nm) + dn * __expf(mo - nm);
            m[h] = nm;
        }
        inv[h] = 1.f / fmaxf(den[h], 1e-9f);
    }

    if (HD == 256) {
        const bool up = (lane & 16);
        const float m_a = up ? m[1] : m[0],  m_b = up ? m[3] : m[2];
        const float i_a = up ? inv[1] : inv[0], i_b = up ? inv[3] : inv[2];
        const float e_a = up ? erh[1] : erh[0], e_b = up ? erh[3] : erh[2];
        float4 acc0 = make_float4(0.f, 0.f, 0.f, 0.f);
        float4 acc1 = make_float4(0.f, 0.f, 0.f, 0.f);
        int j = beg;
        for (; j + 4 <= end; j += 4) {
            int s0 = __ldg(csrc + j), s1 = __ldg(csrc + j + 1);
            int s2 = __ldg(csrc + j + 2), s3 = __ldg(csrc + j + 3);
            const float4* fr0 = (const float4*)(feat + (size_t)s0 * 256);
            const float4* fr1 = (const float4*)(feat + (size_t)s1 * 256);
            const float4* fr2 = (const float4*)(feat + (size_t)s2 * 256);
            const float4* fr3 = (const float4*)(feat + (size_t)s3 * 256);
            float4 f00 = __ldg(fr0 + lane), f01 = __ldg(fr0 + 32 + lane);
            float4 f10 = __ldg(fr1 + lane), f11 = __ldg(fr1 + 32 + lane);
            float4 f20 = __ldg(fr2 + lane), f21 = __ldg(fr2 + 32 + lane);
            float4 f30 = __ldg(fr3 + lane), f31 = __ldg(fr3 + 32 + lane);
            float4 e40 = __ldg((const float4*)el + s0);
            float4 e41 = __ldg((const float4*)el + s1);
            float4 e42 = __ldg((const float4*)el + s2);
            float4 e43 = __ldg((const float4*)el + s3);
            float v0a = (up ? e40.y : e40.x) + e_a; v0a = (v0a > 0.f) ? v0a : 0.2f * v0a;
            float v0b = (up ? e40.w : e40.z) + e_b; v0b = (v0b > 0.f) ? v0b : 0.2f * v0b;
            float v1a = (up ? e41.y : e41.x) + e_a; v1a = (v1a > 0.f) ? v1a : 0.2f * v1a;
            float v1b = (up ? e41.w : e41.z) + e_b; v1b = (v1b > 0.f) ? v1b : 0.2f * v1b;
            float v2a = (up ? e42.y : e42.x) + e_a; v2a = (v2a > 0.f) ? v2a : 0.2f * v2a;
            float v2b = (up ? e42.w : e42.z) + e_b; v2b = (v2b > 0.f) ? v2b : 0.2f * v2b;
            float v3a = (up ? e43.y : e43.x) + e_a; v3a = (v3a > 0.f) ? v3a : 0.2f * v3a;
            float v3b = (up ? e43.w : e43.z) + e_b; v3b = (v3b > 0.f) ? v3b : 0.2f * v3b;
            float a0a = __expf(v0a - m_a) * i_a, a0b = __expf(v0b - m_b) * i_b;
            float a1a = __expf(v1a - m_a) * i_a, a1b = __expf(v1b - m_b) * i_b;
            float a2a = __expf(v2a - m_a) * i_a, a2b = __expf(v2b - m_b) * i_b;
            float a3a = __expf(v3a - m_a) * i_a, a3b = __expf(v3b - m_b) * i_b;
            acc0.x += f00.x * a0a + f10.x * a1a + f20.x * a2a + f30.x * a3a;
            acc0.y += f00.y * a0a + f10.y * a1a + f20.y * a2a + f30.y * a3a;
            acc0.z += f00.z * a0a + f10.z * a1a + f20.z * a2a + f30.z * a3a;
            acc0.w += f00.w * a0a + f10.w * a1a + f20.w * a2a + f30.w * a3a;
            acc1.x += f01.x * a0b + f11.x * a1b + f21.x * a2b + f31.x * a3b;
            acc1.y += f01.y * a0b + f11.y * a1b + f21.y * a2b + f31.y * a3b;
            acc1.z += f01.z * a0b + f11.z * a1b + f21.z * a2b + f31.z * a3b;
            acc1.w += f01.w * a0b + f11.w * a1b + f21.w * a2b + f31.w * a3b;
        }
        for (; j < end; j++) {
            int s0 = __ldg(csrc + j);
            const float4* fr0 = (const float4*)(feat + (size_t)s0 * 256);
            float4 f00 = __ldg(fr0 + lane), f01 = __ldg(fr0 + 32 + lane);
            float4 e40 = __ldg((const float4*)el + s0);
            float v0a = (up ? e40.y : e40.x) + e_a; v0a = (v0a > 0.f) ? v0a : 0.2f * v0a;
            float v0b = (up ? e40.w : e40.z) + e_b; v0b = (v0b > 0.f) ? v0b : 0.2f * v0b;
            float a0a = __expf(v0a - m_a) * i_a, a0b = __expf(v0b - m_b) * i_b;
            acc0.x += f00.x * a0a; acc0.y += f00.y * a0a; acc0.z += f00.z * a0a; acc0.w += f00.w * a0a;
            acc1.x += f01.x * a0b; acc1.y += f01.y * a0b; acc1.z += f01.z * a0b; acc1.w += f01.w * a0b;
        }
#pragma unroll
        for (int q = 0; q < 2; q++) {
            float4 v = q ? acc1 : acc0;
            if (act) {
                v.x = (v.x > 0.f) ? v.x : expm1f(v.x);
                v.y = (v.y > 0.f) ? v.y : expm1f(v.y);
                v.z = (v.z > 0.f) ? v.z : expm1f(v.z);
                v.w = (v.w > 0.f) ? v.w : expm1f(v.w);
            }
            size_t idx = (size_t)warp * 256 + q * 128 + lane * 4;
            if (WM == 0) {
                *(float4*)(out + idx) = v;
            } else {
                __nv_bfloat16 hx = __float2bfloat16(v.x), hy = __float2bfloat16(v.y);
                __nv_bfloat16 hz = __float2bfloat16(v.z), hw = __float2bfloat16(v.w);
                __nv_bfloat162* ph = (__nv_bfloat162*)(ohi + idx);
                __nv_bfloat162* pl = (__nv_bfloat162*)(olo + idx);
                ph[0] = __nv_bfloat162(hx, hy);
                ph[1] = __nv_bfloat162(hz, hw);
                pl[0] = __nv_bfloat162(__float2bfloat16(v.x - __bfloat162float(hx)),
                                       __float2bfloat16(v.y - __bfloat162float(hy)));
                pl[1] = __nv_bfloat162(__float2bfloat16(v.z - __bfloat162float(hz)),
                                       __float2bfloat16(v.w - __bfloat162float(hw)));
            }
        }
    } else {
        // H==1: two 16-lane gangs, 4-edge unroll per gang
        constexpr int NV = HD / 4;
        const int gp = lane >> 4, gl = lane & 15;
        const float m0 = m[0], i0 = inv[0], e0 = erh[0];
        float4 acc = make_float4(0.f, 0.f, 0.f, 0.f);
        int j = beg + gp;
        for (; j + 6 < end; j += 8) {
            int s0 = __ldg(csrc + j),     s1 = __ldg(csrc + j + 2);
            int s2 = __ldg(csrc + j + 4), s3 = __ldg(csrc + j + 6);
            float el0 = __ldg(el + s0), el1 = __ldg(el + s1);
            float el2 = __ldg(el + s2), el3 = __ldg(el + s3);
            float4 f0 = make_float4(0.f, 0.f, 0.f, 0.f), f1 = f0, f2 = f0, f3 = f0;
            if (gl < NV) {
                f0 = __ldg((const float4*)(feat + (size_t)s0 * HD) + gl);
                f1 = __ldg((const float4*)(feat + (size_t)s1 * HD) + gl);
                f2 = __ldg((const float4*)(feat + (size_t)s2 * HD) + gl);
                f3 = __ldg((const float4*)(feat + (size_t)s3 * HD) + gl);
            }
            float v0 = el0 + e0; v0 = (v0 > 0.f) ? v0 : 0.2f * v0;
            float v1 = el1 + e0; v1 = (v1 > 0.f) ? v1 : 0.2f * v1;
            float v2 = el2 + e0; v2 = (v2 > 0.f) ? v2 : 0.2f * v2;
            float v3 = el3 + e0; v3 = (v3 > 0.f) ? v3 : 0.2f * v3;
            float a0 = __expf(v0 - m0) * i0, a1 = __expf(v1 - m0) * i0;
            float a2 = __expf(v2 - m0) * i0, a3 = __expf(v3 - m0) * i0;
            acc.x += f0.x * a0 + f1.x * a1 + f2.x * a2 + f3.x * a3;
            acc.y += f0.y * a0 + f1.y * a1 + f2.y * a2 + f3.y * a3;
            acc.z += f0.z * a0 + f1.z * a1 + f2.z * a2 + f3.z * a3;
            acc.w += f0.w * a0 + f1.w * a1 + f2.w * a2 + f3.w * a3;
        }
        for (; j < end; j += 2) {
            int s0 = __ldg(csrc + j);
            float el0 = __ldg(el + s0);
            float4 f0 = make_float4(0.f, 0.f, 0.f, 0.f);
            if (gl < NV) f0 = __ldg((const float4*)(feat + (size_t)s0 * HD) + gl);
            float v0 = el0 + e0; v0 = (v0 > 0.f) ? v0 : 0.2f * v0;
            float a0 = __expf(v0 - m0) * i0;
            acc.x += f0.x * a0; acc.y += f0.y * a0; acc.z += f0.z * a0; acc.w += f0.w * a0;
        }
        acc.x += __shfl_xor_sync(0xffffffffu, acc.x, 16);
        acc.y += __shfl_xor_sync(0xffffffffu, acc.y, 16);
        acc.z += __shfl_xor_sync(0xffffffffu, acc.z, 16);
        acc.w += __shfl_xor_sync(0xffffffffu, acc.w, 16);
        if (lane < NV) {
            if (act) {
                acc.x = (acc.x > 0.f) ? acc.x : expm1f(acc.x);
                acc.y = (acc.y > 0.f) ? acc.y : expm1f(acc.y);
                acc.z = (acc.z > 0.f) ? acc.z : expm1f(acc.z);
                acc.w = (acc.w > 0.f) ? acc.w : expm1f(acc.w);
            }
            size_t idx = (size_t)warp * HD + lane * 4;
            if (WM == 0) {
                *(float4*)(out + idx) = acc;
            } else {
                __nv_bfloat16 hx = __float2bfloat16(acc.x), hy = __float2bfloat16(acc.y);
                __nv_bfloat16 hz = __float2bfloat16(acc.z), hw = __float2bfloat16(acc.w);
                __nv_bfloat162* ph = (__nv_bfloat162*)(ohi + idx);
                __nv_bfloat162* pl = (__nv_bfloat162*)(olo + idx);
                ph[0] = __nv_bfloat162(hx, hy);
                ph[1] = __nv_bfloat162(hz, hw);
                pl[0] = __nv_bfloat162(__float2bfloat16(acc.x - __bfloat162float(hx)),
                                       __float2bfloat16(acc.y - __bfloat162float(hy)));
                pl[1] = __nv_bfloat162(__float2bfloat16(acc.z - __bfloat162float(hz)),
                                       __float2bfloat16(acc.w - __bfloat162float(hw)));
            }
        }
    }
}

extern "C" void kernel_launch(void* const* d_in, const int* in_sizes, int n_in,
                              void* d_out, int out_size) {
    const float* x    = (const float*)d_in[0];
    const int*   src  = (const int*)d_in[1];
    const int*   dst  = (const int*)d_in[2];
    const float* W00  = (const float*)d_in[3];
    const float* a00l = (const float*)d_in[4];
    const float* a00r = (const float*)d_in[5];
    const float* W01  = (const float*)d_in[6];
    const float* a01l = (const float*)d_in[7];
    const float* a01r = (const float*)d_in[8];
    const float* W0f  = (const float*)d_in[9];
    const float* a0fl = (const float*)d_in[10];
    const float* a0fr = (const float*)d_in[11];
    const float* W10  = (const float*)d_in[12];
    const float* a10l = (const float*)d_in[13];
    const float* a10r = (const float*)d_in[14];
    const float* W1f  = (const float*)d_in[15];
    const float* a1fl = (const float*)d_in[16];
    const float* a1fr = (const float*)d_in[17];
    const float* W1o  = (const float*)d_in[18];
    const float* a1ol = (const float*)d_in[19];
    const float* a1or = (const float*)d_in[20];
    float* out = (float*)d_out;

    const int N = in_sizes[0] / 256;
    const int E = in_sizes[1];

    float *feat0, *feat1, *el0, *er0, *el1, *er1;
    __nv_bfloat16 *xhi, *xlo, *hhi0, *hlo0, *hhi1, *hlo1, *whi0, *wlo0, *whi1, *wlo1;
    int *deg, *rowptr, *wp, *bsum, *csrc;
    cudaGetSymbolAddress((void**)&feat0, g_feat0);
    cudaGetSymbolAddress((void**)&feat1, g_feat1);
    cudaGetSymbolAddress((void**)&el0, g_el0);
    cudaGetSymbolAddress((void**)&er0, g_er0);
    cudaGetSymbolAddress((void**)&el1, g_el1);
    cudaGetSymbolAddress((void**)&er1, g_er1);
    cudaGetSymbolAddress((void**)&xhi, g_xhi);
    cudaGetSymbolAddress((void**)&xlo, g_xlo);
    cudaGetSymbolAddress((void**)&hhi0, g_hhi0);
    cudaGetSymbolAddress((void**)&hlo0, g_hlo0);
    cudaGetSymbolAddress((void**)&hhi1, g_hhi1);
    cudaGetSymbolAddress((void**)&hlo1, g_hlo1);
    cudaGetSymbolAddress((void**)&whi0, g_whi0);
    cudaGetSymbolAddress((void**)&wlo0, g_wlo0);
    cudaGetSymbolAddress((void**)&whi1, g_whi1);
    cudaGetSymbolAddress((void**)&wlo1, g_wlo1);
    cudaGetSymbolAddress((void**)&deg, g_deg);
    cudaGetSymbolAddress((void**)&rowptr, g_rowptr);
    cudaGetSymbolAddress((void**)&wp, g_wp);
    cudaGetSymbolAddress((void**)&bsum, g_bsum);
    cudaGetSymbolAddress((void**)&csrc, g_csrc);

    // ---- prelude: x split + CSR build ----
    split_k<<<((long)N * 256 + 255) / 256, 256>>>(x, xhi, xlo, N * 256);
    zero_deg<<<(N + 255) / 256, 256>>>(deg, N);
    hist_k<<<(E + 255) / 256, 256>>>(dst, deg, E);
    int ntiles = (N + 1023) / 1024;
    scan_tiles<<<ntiles, 1024>>>(deg, rowptr, bsum, N);
    scan_bsum<<<1, 32>>>(bsum, ntiles);
    add_off<<<(N + 255) / 256, 256>>>(rowptr, wp, bsum, N, E);
    scatter_k<<<(E + 255) / 256, 256>>>(src, dst, wp, csrc, E);

    const int aggGridX = (N * 32 + 255) / 256;

    // ===== layer 1: SEQUENTIAL per branch (51MB feat per branch must stay L2-resident
    // during its agg; batching both thrashes L2 — measured +456us in round 15) =====
    prepw_k<<<dim3((256 * 256 + 255) / 256, 2), 256>>>(W00, W10, whi0, wlo0, whi1, wlo1,
                                                       256, 256, 256);
    {
        // branch 0: gemm -> agg (feat0 consumed while L2-hot)
        GemmArgs ga = {};
        ga.Ahi[0] = xhi;  ga.Alo[0] = xlo;
        ga.Bhi[0] = whi0; ga.Blo[0] = wlo0;
        ga.al[0] = a00l; ga.ar[0] = a00r;
        ga.C[0] = feat0; ga.el[0] = el0; ga.er[0] = er0;
        gemm_mma<256, 256, 64><<<dim3(4, (N + 127) / 128, 1), 256>>>(ga, N);
        AggArgs aa = {};
        aa.el[0] = el0; aa.er[0] = er0; aa.feat[0] = feat0;
        aa.ohi[0] = hhi0; aa.olo[0] = hlo0; aa.act[0] = 1;
        agg_k<4, 64, 1><<<dim3(aggGridX, 1), 256>>>(rowptr, csrc, aa, N);
    }
    {
        // branch 1
        GemmArgs ga = {};
        ga.Ahi[0] = xhi;  ga.Alo[0] = xlo;
        ga.Bhi[0] = whi1; ga.Blo[0] = wlo1;
        ga.al[0] = a10l; ga.ar[0] = a10r;
        ga.C[0] = feat1; ga.el[0] = el1; ga.er[0] = er1;
        gemm_mma<256, 256, 64><<<dim3(4, (N + 127) / 128, 1), 256>>>(ga, N);
        AggArgs aa = {};
        aa.el[0] = el1; aa.er[0] = er1; aa.feat[0] = feat1;
        aa.ohi[0] = hhi1; aa.olo[0] = hlo1; aa.act[0] = 1;
        agg_k<4, 64, 1><<<dim3(aggGridX, 1), 256>>>(rowptr, csrc, aa, N);
    }

    // ===== layer 2 BATCHED (H=1, K=256, J=64; feat 12.8MB/branch — L2-safe) =====
    {
        prepw_k<<<dim3((256 * 64 + 255) / 256, 2), 256>>>(W01, W1f, whi0, wlo0, whi1, wlo1,
                                                          256, 64, 64);
        GemmArgs ga = {};
        ga.Ahi[0] = hhi0; ga.Alo[0] = hlo0; ga.Ahi[1] = hhi1; ga.Alo[1] = hlo1;
        ga.Bhi[0] = whi0; ga.Blo[0] = wlo0; ga.Bhi[1] = whi1; ga.Blo[1] = wlo1;
        ga.al[0] = a01l; ga.ar[0] = a01r; ga.al[1] = a1fl; ga.ar[1] = a1fr;
        ga.C[0] = feat0; ga.el[0] = el0; ga.er[0] = er0;
        ga.C[1] = feat1; ga.el[1] = el1; ga.er[1] = er1;
        gemm_mma<256, 64, 64><<<dim3(1, (N + 127) / 128, 2), 256>>>(ga, N);
        AggArgs aa = {};
        aa.el[0] = el0; aa.er[0] = er0; aa.feat[0] = feat0;
        aa.ohi[0] = hhi0; aa.olo[0] = hlo0; aa.act[0] = 1;
        aa.el[1] = el1; aa.er[1] = er1; aa.feat[1] = feat1;
        aa.ohi[1] = hhi1; aa.olo[1] = hlo1; aa.act[1] = 0;
        agg_k<1, 64, 1><<<dim3(aggGridX, 2), 256>>>(rowptr, csrc, aa, N);
    }

    // ===== layer 3 BATCHED (H=1, K=64, J=40; feat 8MB/branch) =====
    {
        prepw_k<<<dim3((64 * 64 + 255) / 256, 2), 256>>>(W0f, W1o, whi0, wlo0, whi1, wlo1,
                                                         64, 40, 64);
        GemmArgs ga = {};
        ga.Ahi[0] = hhi0; ga.Alo[0] = hlo0; ga.Ahi[1] = hhi1; ga.Alo[1] = hlo1;
        ga.Bhi[0] = whi0; ga.Blo[0] = wlo0; ga.Bhi[1] = whi1; ga.Blo[1] = wlo1;
        ga.al[0] = a0fl; ga.ar[0] = a0fr; ga.al[1] = a1ol; ga.ar[1] = a1or;
        ga.C[0] = feat0; ga.el[0] = el0; ga.er[0] = er0;
        ga.C[1] = feat1; ga.el[1] = el1; ga.er[1] = er1;
        gemm_mma<64, 40, 40><<<dim3(1, (N + 127) / 128, 2), 256>>>(ga, N);
        AggArgs aa = {};
        aa.el[0] = el0; aa.er[0] = er0; aa.feat[0] = feat0;
        aa.out[0] = out; aa.act[0] = 0;
        aa.el[1] = el1; aa.er[1] = er1; aa.feat[1] = feat1;
        aa.out[1] = out + (size_t)N * CC; aa.act[1] = 1;
        agg_k<1, 40, 0><<<dim3(aggGridX, 2), 256>>>(rowptr, csrc, aa, N);
    }
}

// round 17
// speedup vs baseline: 1.7056x; 1.2131x over previous
#include <cuda_runtime.h>
#include <cuda_bf16.h>
#include <math.h>
#include <stdint.h>

#define NN 50000
#define EE 800000
#define CC 40

// ---------------- scratch (device globals; no allocations allowed) ----------------
__device__ __align__(16) float g_feat[NN * 256];           // GEMM output (fp32)
__device__ __align__(16) float g_el[NN * 4];
__device__ __align__(16) float g_er[NN * 4];
__device__ __align__(16) __nv_bfloat16 g_xhi[NN * 256];    // x split (built once)
__device__ __align__(16) __nv_bfloat16 g_xlo[NN * 256];
__device__ __align__(16) __nv_bfloat16 g_hhi[NN * 256];    // intermediate split
__device__ __align__(16) __nv_bfloat16 g_hlo[NN * 256];
__device__ __align__(16) __nv_bfloat16 g_whi[256 * 256];   // W^T split (padded)
__device__ __align__(16) __nv_bfloat16 g_wlo[256 * 256];
__device__ int   g_deg[NN];
__device__ int   g_rowptr[NN + 1];
__device__ int   g_wp[NN];
__device__ int   g_bsum[64];
__device__ int   g_csrc[EE];

__device__ __forceinline__ uint32_t s2u(const void* p) {
    uint32_t a;
    asm("{ .reg .u64 t; cvta.to.shared.u64 t, %1; cvt.u32.u64 %0, t; }" : "=r"(a) : "l"(p));
    return a;
}

// ================= CSR build =================
__global__ void zero_deg(int* deg, int N) {
    int i = blockIdx.x * blockDim.x + threadIdx.x;
    if (i < N) deg[i] = 0;
}
__global__ void hist_k(const int* __restrict__ dst, int* __restrict__ deg, int E) {
    int i = blockIdx.x * blockDim.x + threadIdx.x;
    if (i < E) atomicAdd(&deg[dst[i]], 1);
}
__global__ void scan_tiles(const int* __restrict__ deg, int* __restrict__ rowptr,
                           int* __restrict__ bsum, int N) {
    __shared__ int sh[1024];
    int i = blockIdx.x * 1024 + threadIdx.x;
    int v = (i < N) ? deg[i] : 0;
    sh[threadIdx.x] = v;
    __syncthreads();
    for (int o = 1; o < 1024; o <<= 1) {
        int t = (threadIdx.x >= o) ? sh[threadIdx.x - o] : 0;
        __syncthreads();
        sh[threadIdx.x] += t;
        __syncthreads();
    }
    if (i < N) rowptr[i] = sh[threadIdx.x] - v;
    if (threadIdx.x == 1023) bsum[blockIdx.x] = sh[1023];
}
__global__ void scan_bsum(int* bsum, int nb) {
    if (threadIdx.x == 0 && blockIdx.x == 0) {
        int acc = 0;
        for (int b = 0; b < nb; b++) { int t = bsum[b]; bsum[b] = acc; acc += t; }
    }
}
__global__ void add_off(int* __restrict__ rowptr, int* __restrict__ wp,
                        const int* __restrict__ bsum, int N, int E) {
    int i = blockIdx.x * blockDim.x + threadIdx.x;
    if (i < N) {
        int v = rowptr[i] + bsum[i >> 10];
        rowptr[i] = v;
        wp[i] = v;
    }
    if (i == 0) rowptr[N] = E;
}
__global__ void scatter_k(const int* __restrict__ src, const int* __restrict__ dst,
                          int* __restrict__ wp, int* __restrict__ csrc, int E) {
    int i = blockIdx.x * blockDim.x + threadIdx.x;
    if (i < E) {
        int pos = atomicAdd(&wp[dst[i]], 1);
        csrc[pos] = src[i];
    }
}

// ================= split / W-prep =================
__global__ void split_k(const float* __restrict__ v, __nv_bfloat16* __restrict__ hi,
                        __nv_bfloat16* __restrict__ lo, int n) {
    int i = blockIdx.x * blockDim.x + threadIdx.x;
    if (i < n) {
        float f = v[i];
        __nv_bfloat16 h = __float2bfloat16(f);
        hi[i] = h;
        lo[i] = __float2bfloat16(f - __bfloat162float(h));
    }
}
__global__ void prepw_k(const float* __restrict__ W, __nv_bfloat16* __restrict__ hi,
                        __nv_bfloat16* __restrict__ lo, int K, int J, int J64) {
    int i = blockIdx.x * blockDim.x + threadIdx.x;
    if (i < K * J64) {
        int j = i / K, k = i % K;
        float f = (j < J) ? W[k * J + j] : 0.f;
        __nv_bfloat16 h = __float2bfloat16(f);
        hi[i] = h;
        lo[i] = __float2bfloat16(f - __bfloat162float(h));
    }
}

// ================= mma.sync bf16 GEMM, ldmatrix, fused scores epilogue =================
#define MMA_BF16(d, a, b)                                                          \
    asm volatile(                                                                  \
        "mma.sync.aligned.m16n8k16.row.col.f32.bf16.bf16.f32 "                     \
        "{%0,%1,%2,%3},{%4,%5,%6,%7},{%8,%9},{%0,%1,%2,%3};"                       \
        : "+f"((d)[0]), "+f"((d)[1]), "+f"((d)[2]), "+f"((d)[3])                   \
        : "r"((a)[0]), "r"((a)[1]), "r"((a)[2]), "r"((a)[3]), "r"((b)[0]), "r"((b)[1]))
#define LDSM4(r, addr)                                                             \
    asm volatile("ldmatrix.sync.aligned.m8n8.x4.shared.b16 {%0,%1,%2,%3}, [%4];"   \
        : "=r"((r)[0]), "=r"((r)[1]), "=r"((r)[2]), "=r"((r)[3]) : "r"(addr))

template <int K, int J, int D>
__global__ __launch_bounds__(256) void gemm_mma(
    const __nv_bfloat16* __restrict__ Ahi, const __nv_bfloat16* __restrict__ Alo,
    const __nv_bfloat16* __restrict__ Bhi, const __nv_bfloat16* __restrict__ Blo,
    const float* __restrict__ alv, const float* __restrict__ arv,
    float* __restrict__ C, float* __restrict__ el, float* __restrict__ er, int M) {
    constexpr int H = J / D;
    constexpr int BK = 32, STR = BK + 8;
    __shared__ __nv_bfloat16 sAh[128 * STR], sAl[128 * STR];
    __shared__ __nv_bfloat16 sBh[64 * STR], sBl[64 * STR];
    __shared__ float sEl[128][2], sEr[128][2];
    const int tid = threadIdx.x;
    const int wid = tid >> 5, lane = tid & 31;
    const int g = lane >> 2, t = lane & 3;
    const int wm = wid & 3, wn = wid >> 2;
    const int row0 = blockIdx.y * 128, col0 = blockIdx.x * 64;

    float acc[2][4][4];
#pragma unroll
    for (int am = 0; am < 2; am++)
#pragma unroll
        for (int an = 0; an < 4; an++)
#pragma unroll
            for (int q = 0; q < 4; q++) acc[am][an][q] = 0.f;

    uint4 rah[2], ral[2], rbh, rbl;
    const int ar0 = tid >> 2, acb0 = (tid & 3) * 8;
    const int ar1 = (tid + 256) >> 2, acb1 = ((tid + 256) & 3) * 8;
    const int gra0 = min(row0 + ar0, M - 1), gra1 = min(row0 + ar1, M - 1);
    const int brr = tid >> 2, bcb = (tid & 3) * 8;

#define LOADREG(kb)                                                                  \
    do {                                                                             \
        rah[0] = *(const uint4*)&Ahi[(size_t)gra0 * K + (kb) + acb0];                \
        ral[0] = *(const uint4*)&Alo[(size_t)gra0 * K + (kb) + acb0];                \
        rah[1] = *(const uint4*)&Ahi[(size_t)gra1 * K + (kb) + acb1];                \
        ral[1] = *(const uint4*)&Alo[(size_t)gra1 * K + (kb) + acb1];                \
        rbh = *(const uint4*)&Bhi[(size_t)(col0 + brr) * K + (kb) + bcb];            \
        rbl = *(const uint4*)&Blo[(size_t)(col0 + brr) * K + (kb) + bcb];            \
    } while (0)

    const uint32_t uAh = s2u(sAh), uAl = s2u(sAl), uBh = s2u(sBh), uBl = s2u(sBl);
    const int lar = ((lane >> 3) & 1) * 8 + (lane & 7);
    const int lak = (lane >> 4) * 8;
    const uint32_t aoff = (uint32_t)((lar * STR + lak) * 2);
    const uint32_t amo0 = (uint32_t)((wm * 32) * STR * 2);
    const uint32_t amo1 = amo0 + (uint32_t)(16 * STR * 2);
    const int bn = lane & 7, bk2 = ((lane >> 3) & 1) * 8, bsel = lane >> 4;
    uint32_t boff[2];
#pragma unroll
    for (int p = 0; p < 2; p++)
        boff[p] = (uint32_t)(((wn * 32 + (2 * p + bsel) * 8 + bn) * STR + bk2) * 2);

    LOADREG(0);
    for (int kb = 0; kb < K; kb += BK) {
        *(uint4*)&sAh[ar0 * STR + acb0] = rah[0];
        *(uint4*)&sAl[ar0 * STR + acb0] = ral[0];
        *(uint4*)&sAh[ar1 * STR + acb1] = rah[1];
        *(uint4*)&sAl[ar1 * STR + acb1] = ral[1];
        *(uint4*)&sBh[brr * STR + bcb] = rbh;
        *(uint4*)&sBl[brr * STR + bcb] = rbl;
        __syncthreads();
        if (kb + BK < K) LOADREG(kb + BK);
#pragma unroll
        for (int ks = 0; ks < BK / 16; ks++) {
            const uint32_t k2 = (uint32_t)(ks * 16 * 2);
            uint32_t ah[2][4], al_[2][4], bh[2][4], bl[2][4];
            LDSM4(ah[0], uAh + amo0 + aoff + k2);
            LDSM4(ah[1], uAh + amo1 + aoff + k2);
            LDSM4(al_[0], uAl + amo0 + aoff + k2);
            LDSM4(al_[1], uAl + amo1 + aoff + k2);
            LDSM4(bh[0], uBh + boff[0] + k2);
            LDSM4(bh[1], uBh + boff[1] + k2);
            LDSM4(bl[0], uBl + boff[0] + k2);
            LDSM4(bl[1], uBl + boff[1] + k2);
#pragma unroll
            for (int am = 0; am < 2; am++)
#pragma unroll
                for (int an = 0; an < 4; an++) {
                    uint32_t* bph = &bh[an >> 1][(an & 1) * 2];
                    uint32_t* bpl = &bl[an >> 1][(an & 1) * 2];
                    MMA_BF16(acc[am][an], ah[am], bph);
                    MMA_BF16(acc[am][an], ah[am], bpl);
                    MMA_BF16(acc[am][an], al_[am], bph);
                }
        }
        __syncthreads();
    }
#undef LOADREG

    // ---- store C + fused attention scores (smem cross-warp reduce, no atomics) ----
    const int head = (col0 + wn * 32) / D;
    float alc[4][2], arc[4][2];
#pragma unroll
    for (int an = 0; an < 4; an++) {
        int c = col0 + wn * 32 + an * 8 + 2 * t;
#pragma unroll
        for (int q = 0; q < 2; q++) {
            alc[an][q] = (c + q < J) ? __ldg(alv + c + q) : 0.f;
            arc[an][q] = (c + q < J) ? __ldg(arv + c + q) : 0.f;
        }
    }
#pragma unroll
    for (int am = 0; am < 2; am++) {
        int r0 = row0 + wm * 32 + am * 16 + g;
        float pl0 = 0.f, pr0 = 0.f, pl8 = 0.f, pr8 = 0.f;
#pragma unroll
        for (int an = 0; an < 4; an++) {
            int c = col0 + wn * 32 + an * 8 + 2 * t;
            if (c < J) {
                if (r0 < M)
                    *(float2*)&C[(size_t)r0 * J + c] = make_float2(acc[am][an][0], acc[am][an][1]);
                if (r0 + 8 < M)
                    *(float2*)&C[(size_t)(r0 + 8) * J + c] = make_float2(acc[am][an][2], acc[am][an][3]);
            }
            pl0 += acc[am][an][0] * alc[an][0] + acc[am][an][1] * alc[an][1];
            pr0 += acc[am][an][0] * arc[an][0] + acc[am][an][1] * arc[an][1];
            pl8 += acc[am][an][2] * alc[an][0] + acc[am][an][3] * alc[an][1];
            pr8 += acc[am][an][2] * arc[an][0] + acc[am][an][3] * arc[an][1];
        }
#pragma unroll
        for (int o = 1; o < 4; o <<= 1) {
            pl0 += __shfl_xor_sync(0xffffffffu, pl0, o);
            pr0 += __shfl_xor_sync(0xffffffffu, pr0, o);
            pl8 += __shfl_xor_sync(0xffffffffu, pl8, o);
            pr8 += __shfl_xor_sync(0xffffffffu, pr8, o);
        }
        if (t == 0) {
            int rl = wm * 32 + am * 16 + g;
            sEl[rl][wn] = pl0; sEr[rl][wn] = pr0;
            sEl[rl + 8][wn] = pl8; sEr[rl + 8][wn] = pr8;
        }
    }
    __syncthreads();
    if (tid < 128) {
        int row = row0 + tid;
        if (row < M) {
            el[row * H + head] = sEl[tid][0] + sEl[tid][1];
            er[row * H + head] = sEr[tid][0] + sEr[tid][1];
        }
    }
}

// ================= fused softmax + aggregate (CSR, one warp per dst node) ===========
// HD=256 path: 2-edge unroll (round-12 proven; 4-edge regressed via register pressure).
template <int H, int D, int ACT, int WM>
__global__ __launch_bounds__(256) void agg_k(const int* __restrict__ rowptr,
                                             const int* __restrict__ csrc,
                                             const float* __restrict__ el,
                                             const float* __restrict__ er,
                                             const float* __restrict__ feat,
                                             float* __restrict__ out,
                                             __nv_bfloat16* __restrict__ ohi,
                                             __nv_bfloat16* __restrict__ olo, int N) {
    constexpr int HD = H * D;
    int warp = (blockIdx.x * blockDim.x + threadIdx.x) >> 5;
    int lane = threadIdx.x & 31;
    if (warp >= N) return;
    int beg = rowptr[warp];
    int end = rowptr[warp + 1];

    float erh[H];
    if (H == 4) {
        float4 t = __ldg((const float4*)er + warp);
        erh[0] = t.x; erh[1] = t.y; erh[2] = t.z; erh[3] = t.w;
    } else {
        erh[0] = __ldg(er + warp);
    }

    // ---- online softmax (max + den in one lane-strided pass) ----
    float m[H], den[H];
#pragma unroll
    for (int h = 0; h < H; h++) { m[h] = -1e30f; den[h] = 0.f; }
    for (int j = beg + lane; j < end; j += 32) {
        int s = __ldg(csrc + j);
        float eh[H];
        if (H == 4) {
            float4 t = __ldg((const float4*)el + s);
            eh[0] = t.x; eh[1] = t.y; eh[2] = t.z; eh[3] = t.w;
        } else eh[0] = __ldg(el + s);
#pragma unroll
        for (int h = 0; h < H; h++) {
            float v = eh[h] + erh[h];
            v = (v > 0.f) ? v : 0.2f * v;
            float nm = fmaxf(m[h], v);
            den[h] = den[h] * __expf(m[h] - nm) + __expf(v - nm);
            m[h] = nm;
        }
    }
    float inv[H];
#pragma unroll
    for (int h = 0; h < H; h++) {
#pragma unroll
        for (int o = 16; o; o >>= 1) {
            float mo = __shfl_xor_sync(0xffffffffu, m[h], o);
            float dn = __shfl_xor_sync(0xffffffffu, den[h], o);
            float nm = fmaxf(m[h], mo);
            den[h] = den[h] * __expf(m[h] - nm) + dn * __expf(mo - nm);
            m[h] = nm;
        }
        inv[h] = 1.f / fmaxf(den[h], 1e-9f);
    }

    if (HD == 256) {
        const bool up = (lane & 16);
        const float m_a = up ? m[1] : m[0],  m_b = up ? m[3] : m[2];
        const float i_a = up ? inv[1] : inv[0], i_b = up ? inv[3] : inv[2];
        const float e_a = up ? erh[1] : erh[0], e_b = up ? erh[3] : erh[2];
        float4 acc0 = make_float4(0.f, 0.f, 0.f, 0.f);
        float4 acc1 = make_float4(0.f, 0.f, 0.f, 0.f);
        int j = beg;
        for (; j + 2 <= end; j += 2) {
            int s0 = __ldg(csrc + j), s1 = __ldg(csrc + j + 1);
            const float4* fr0 = (const float4*)(feat + (size_t)s0 * 256);
            const float4* fr1 = (const float4*)(feat + (size_t)s1 * 256);
            float4 f00 = __ldg(fr0 + lane), f01 = __ldg(fr0 + 32 + lane);
            float4 f10 = __ldg(fr1 + lane), f11 = __ldg(fr1 + 32 + lane);
            float4 e40 = __ldg((const float4*)el + s0);
            float4 e41 = __ldg((const float4*)el + s1);
            float v0a = (up ? e40.y : e40.x) + e_a; v0a = (v0a > 0.f) ? v0a : 0.2f * v0a;
            float v0b = (up ? e40.w : e40.z) + e_b; v0b = (v0b > 0.f) ? v0b : 0.2f * v0b;
            float v1a = (up ? e41.y : e41.x) + e_a; v1a = (v1a > 0.f) ? v1a : 0.2f * v1a;
            float v1b = (up ? e41.w : e41.z) + e_b; v1b = (v1b > 0.f) ? v1b : 0.2f * v1b;
            float a0a = __expf(v0a - m_a) * i_a, a0b = __expf(v0b - m_b) * i_b;
            float a1a = __expf(v1a - m_a) * i_a, a1b = __expf(v1b - m_b) * i_b;
            acc0.x += f00.x * a0a; acc0.y += f00.y * a0a; acc0.z += f00.z * a0a; acc0.w += f00.w * a0a;
            acc1.x += f01.x * a0b; acc1.y += f01.y * a0b; acc1.z += f01.z * a0b; acc1.w += f01.w * a0b;
            acc0.x += f10.x * a1a; acc0.y += f10.y * a1a; acc0.z += f10.z * a1a; acc0.w += f10.w * a1a;
            acc1.x += f11.x * a1b; acc1.y += f11.y * a1b; acc1.z += f11.z * a1b; acc1.w += f11.w * a1b;
        }
        if (j < end) {
            int s0 = __ldg(csrc + j);
            const float4* fr0 = (const float4*)(feat + (size_t)s0 * 256);
            float4 f00 = __ldg(fr0 + lane), f01 = __ldg(fr0 + 32 + lane);
            float4 e40 = __ldg((const float4*)el + s0);
            float v0a = (up ? e40.y : e40.x) + e_a; v0a = (v0a > 0.f) ? v0a : 0.2f * v0a;
            float v0b = (up ? e40.w : e40.z) + e_b; v0b = (v0b > 0.f) ? v0b : 0.2f * v0b;
            float a0a = __expf(v0a - m_a) * i_a, a0b = __expf(v0b - m_b) * i_b;
            acc0.x += f00.x * a0a; acc0.y += f00.y * a0a; acc0.z += f00.z * a0a; acc0.w += f00.w * a0a;
            acc1.x += f01.x * a0b; acc1.y += f01.y * a0b; acc1.z += f01.z * a0b; acc1.w += f01.w * a0b;
        }
#pragma unroll
        for (int q = 0; q < 2; q++) {
            float4 v = q ? acc1 : acc0;
            if (ACT) {
                v.x = (v.x > 0.f) ? v.x : expm1f(v.x);
                v.y = (v.y > 0.f) ? v.y : expm1f(v.y);
                v.z = (v.z > 0.f) ? v.z : expm1f(v.z);
                v.w = (v.w > 0.f) ? v.w : expm1f(v.w);
            }
            size_t idx = (size_t)warp * 256 + q * 128 + lane * 4;
            if (WM == 0) {
                *(float4*)(out + idx) = v;
            } else {
                __nv_bfloat16 hx = __float2bfloat16(v.x), hy = __float2bfloat16(v.y);
                __nv_bfloat16 hz = __float2bfloat16(v.z), hw = __float2bfloat16(v.w);
                __nv_bfloat162* ph = (__nv_bfloat162*)(ohi + idx);
                __nv_bfloat162* pl = (__nv_bfloat162*)(olo + idx);
                ph[0] = __nv_bfloat162(hx, hy);
                ph[1] = __nv_bfloat162(hz, hw);
                pl[0] = __nv_bfloat162(__float2bfloat16(v.x - __bfloat162float(hx)),
                                       __float2bfloat16(v.y - __bfloat162float(hy)));
                pl[1] = __nv_bfloat162(__float2bfloat16(v.z - __bfloat162float(hz)),
                                       __float2bfloat16(v.w - __bfloat162float(hw)));
            }
        }
    } else {
        // H==1: two 16-lane gangs, 4-edge unroll per gang (small register budget)
        constexpr int NV = HD / 4;
        const int gp = lane >> 4, gl = lane & 15;
        const float m0 = m[0], i0 = inv[0], e0 = erh[0];
        float4 acc = make_float4(0.f, 0.f, 0.f, 0.f);
        int j = beg + gp;
        for (; j + 6 < end; j += 8) {
            int s0 = __ldg(csrc + j),     s1 = __ldg(csrc + j + 2);
            int s2 = __ldg(csrc + j + 4), s3 = __ldg(csrc + j + 6);
            float el0 = __ldg(el + s0), el1 = __ldg(el + s1);
            float el2 = __ldg(el + s2), el3 = __ldg(el + s3);
            float4 f0 = make_float4(0.f, 0.f, 0.f, 0.f), f1 = f0, f2 = f0, f3 = f0;
            if (gl < NV) {
                f0 = __ldg((const float4*)(feat + (size_t)s0 * HD) + gl);
                f1 = __ldg((const float4*)(feat + (size_t)s1 * HD) + gl);
                f2 = __ldg((const float4*)(feat + (size_t)s2 * HD) + gl);
                f3 = __ldg((const float4*)(feat + (size_t)s3 * HD) + gl);
            }
            float v0 = el0 + e0; v0 = (v0 > 0.f) ? v0 : 0.2f * v0;
            float v1 = el1 + e0; v1 = (v1 > 0.f) ? v1 : 0.2f * v1;
            float v2 = el2 + e0; v2 = (v2 > 0.f) ? v2 : 0.2f * v2;
            float v3 = el3 + e0; v3 = (v3 > 0.f) ? v3 : 0.2f * v3;
            float a0 = __expf(v0 - m0) * i0, a1 = __expf(v1 - m0) * i0;
            float a2 = __expf(v2 - m0) * i0, a3 = __expf(v3 - m0) * i0;
            acc.x += f0.x * a0 + f1.x * a1 + f2.x * a2 + f3.x * a3;
            acc.y += f0.y * a0 + f1.y * a1 + f2.y * a2 + f3.y * a3;
            acc.z += f0.z * a0 + f1.z * a1 + f2.z * a2 + f3.z * a3;
            acc.w += f0.w * a0 + f1.w * a1 + f2.w * a2 + f3.w * a3;
        }
        for (; j < end; j += 2) {
            int s0 = __ldg(csrc + j);
            float el0 = __ldg(el + s0);
            float4 f0 = make_float4(0.f, 0.f, 0.f, 0.f);
            if (gl < NV) f0 = __ldg((const float4*)(feat + (size_t)s0 * HD) + gl);
            float v0 = el0 + e0; v0 = (v0 > 0.f) ? v0 : 0.2f * v0;
            float a0 = __expf(v0 - m0) * i0;
            acc.x += f0.x * a0; acc.y += f0.y * a0; acc.z += f0.z * a0; acc.w += f0.w * a0;
        }
        acc.x += __shfl_xor_sync(0xffffffffu, acc.x, 16);
        acc.y += __shfl_xor_sync(0xffffffffu, acc.y, 16);
        acc.z += __shfl_xor_sync(0xffffffffu, acc.z, 16);
        acc.w += __shfl_xor_sync(0xffffffffu, acc.w, 16);
        if (lane < NV) {
            if (ACT) {
                acc.x = (acc.x > 0.f) ? acc.x : expm1f(acc.x);
                acc.y = (acc.y > 0.f) ? acc.y : expm1f(acc.y);
                acc.z = (acc.z > 0.f) ? acc.z : expm1f(acc.z);
                acc.w = (acc.w > 0.f) ? acc.w : expm1f(acc.w);
            }
            size_t idx = (size_t)warp * HD + lane * 4;
            if (WM == 0) {
                *(float4*)(out + idx) = acc;
            } else {
                __nv_bfloat16 hx = __float2bfloat16(acc.x), hy = __float2bfloat16(acc.y);
                __nv_bfloat16 hz = __float2bfloat16(acc.z), hw = __float2bfloat16(acc.w);
                __nv_bfloat162* ph = (__nv_bfloat162*)(ohi + idx);
                __nv_bfloat162* pl = (__nv_bfloat162*)(olo + idx);
                ph[0] = __nv_bfloat162(hx, hy);
                ph[1] = __nv_bfloat162(hz, hw);
                pl[0] = __nv_bfloat162(__float2bfloat16(acc.x - __bfloat162float(hx)),
                                       __float2bfloat16(acc.y - __bfloat162float(hy)));
                pl[1] = __nv_bfloat162(__float2bfloat16(acc.z - __bfloat162float(hz)),
                                       __float2bfloat16(acc.w - __bfloat162float(hw)));
            }
        }
    }
}

// ================= one full GATConv layer =================
template <int K, int H, int D, int ACT, int WM>
static void run_layer(const __nv_bfloat16* Ahi, const __nv_bfloat16* Alo,
                      const float* W, const float* al, const float* ar,
                      float* feat, float* outf, __nv_bfloat16* ohi, __nv_bfloat16* olo,
                      int N, const int* rowptr, const int* csrc, float* el, float* er,
                      __nv_bfloat16* whi, __nv_bfloat16* wlo) {
    constexpr int J = H * D;
    constexpr int J64 = (J + 63) / 64 * 64;
    prepw_k<<<(K * J64 + 255) / 256, 256>>>(W, whi, wlo, K, J, J64);
    dim3 grid(J64 / 64, (N + 127) / 128);
    gemm_mma<K, J, D><<<grid, 256>>>(Ahi, Alo, whi, wlo, al, ar, feat, el, er, N);
    agg_k<H, D, ACT, WM><<<(N * 32 + 255) / 256, 256>>>(rowptr, csrc, el, er, feat,
                                                        outf, ohi, olo, N);
}

extern "C" void kernel_launch(void* const* d_in, const int* in_sizes, int n_in,
                              void* d_out, int out_size) {
    const float* x    = (const float*)d_in[0];
    const int*   src  = (const int*)d_in[1];
    const int*   dst  = (const int*)d_in[2];
    const float* W00  = (const float*)d_in[3];
    const float* a00l = (const float*)d_in[4];
    const float* a00r = (const float*)d_in[5];
    const float* W01  = (const float*)d_in[6];
    const float* a01l = (const float*)d_in[7];
    const float* a01r = (const float*)d_in[8];
    const float* W0f  = (const float*)d_in[9];
    const float* a0fl = (const float*)d_in[10];
    const float* a0fr = (const float*)d_in[11];
    const float* W10  = (const float*)d_in[12];
    const float* a10l = (const float*)d_in[13];
    const float* a10r = (const float*)d_in[14];
    const float* W1f  = (const float*)d_in[15];
    const float* a1fl = (const float*)d_in[16];
    const float* a1fr = (const float*)d_in[17];
    const float* W1o  = (const float*)d_in[18];
    const float* a1ol = (const float*)d_in[19];
    const float* a1or = (const float*)d_in[20];
    float* out = (float*)d_out;

    const int N = in_sizes[0] / 256;
    const int E = in_sizes[1];

    float *feat, *el, *er;
    __nv_bfloat16 *xhi, *xlo, *hhi, *hlo, *whi, *wlo;
    int *deg, *rowptr, *wp, *bsum, *csrc;
    cudaGetSymbolAddress((void**)&feat, g_feat);
    cudaGetSymbolAddress((void**)&el, g_el);
    cudaGetSymbolAddress((void**)&er, g_er);
    cudaGetSymbolAddress((void**)&xhi, g_xhi);
    cudaGetSymbolAddress((void**)&xlo, g_xlo);
    cudaGetSymbolAddress((void**)&hhi, g_hhi);
    cudaGetSymbolAddress((void**)&hlo, g_hlo);
    cudaGetSymbolAddress((void**)&whi, g_whi);
    cudaGetSymbolAddress((void**)&wlo, g_wlo);
    cudaGetSymbolAddress((void**)&deg, g_deg);
    cudaGetSymbolAddress((void**)&rowptr, g_rowptr);
    cudaGetSymbolAddress((void**)&wp, g_wp);
    cudaGetSymbolAddress((void**)&bsum, g_bsum);
    cudaGetSymbolAddress((void**)&csrc, g_csrc);

    // ---- x split + dst-CSR build (shared by all layers) ----
    split_k<<<((long)N * 256 + 255) / 256, 256>>>(x, xhi, xlo, N * 256);
    zero_deg<<<(N + 255) / 256, 256>>>(deg, N);
    hist_k<<<(E + 255) / 256, 256>>>(dst, deg, E);
    int ntiles = (N + 1023) / 1024;
    scan_tiles<<<ntiles, 1024>>>(deg, rowptr, bsum, N);
    scan_bsum<<<1, 32>>>(bsum, ntiles);
    add_off<<<(N + 255) / 256, 256>>>(rowptr, wp, bsum, N, E);
    scatter_k<<<(E + 255) / 256, 256>>>(src, dst, wp, csrc, E);

    // ---- branch 0 (fully sequential; single feat buffer keeps L2 behavior of r12) ----
    run_layer<256, 4, 64, 1, 1>(xhi, xlo, W00, a00l, a00r, feat, nullptr, hhi, hlo,
                                N, rowptr, csrc, el, er, whi, wlo);
    run_layer<256, 1, 64, 1, 1>(hhi, hlo, W01, a01l, a01r, feat, nullptr, hhi, hlo,
                                N, rowptr, csrc, el, er, whi, wlo);
    run_layer<64, 1, 40, 0, 0>(hhi, hlo, W0f, a0fl, a0fr, feat, out, nullptr, nullptr,
                               N, rowptr, csrc, el, er, whi, wlo);

    // ---- branch 1 ----
    run_layer<256, 4, 64, 1, 1>(xhi, xlo, W10, a10l, a10r, feat, nullptr, hhi, hlo,
                                N, rowptr, csrc, el, er, whi, wlo);
    run_layer<256, 1, 64, 0, 1>(hhi, hlo, W1f, a1fl, a1fr, feat, nullptr, hhi, hlo,
                                N, rowptr, csrc, el, er, whi, wlo);
    run_layer<64, 1, 40, 1, 0>(hhi, hlo, W1o, a1ol, a1or, feat, out + (size_t)N * CC,
                               nullptr, nullptr, N, rowptr, csrc, el, er, whi, wlo);
}